// round 3
// baseline (speedup 1.0000x reference)
#include <cuda_runtime.h>

#define NN    8192
#define K0    16
#define MM    3072
#define KNNK  15
#define TT    1024
#define NTRI  43008      // MM * 14
#define KT    20
#define HID   128
#define SORTN 65536

// ---------------- scratch (static device globals; no allocation) ----------------
__device__ unsigned long long g_keysN[NN];     // stage-2 sort keys
__device__ float              g_ext[MM * 3];   // selected points
__device__ int                g_knn[MM * KNNK];
__device__ float              g_f[MM];
__device__ float              g_S[MM * KNNK];
__device__ float              g_p[NTRI];
__device__ float              g_bary[NTRI * 3];
__device__ unsigned long long g_sort[SORTN];   // stage-10 sort keys (padded)

// order-preserving float->u32 map, then invert for DESCENDING sort via ascending keys
__device__ __forceinline__ unsigned fdesc(float v) {
    unsigned fb  = __float_as_uint(v);
    unsigned asc = (fb & 0x80000000u) ? ~fb : (fb | 0x80000000u);
    return ~asc;
}

// ---------------- Stage 1: GNN inclusion scores ----------------
__global__ void k_gnn(const float* __restrict__ nodes, const int* __restrict__ adj,
                      const float* __restrict__ Wg, const float* __restrict__ wg) {
    int i = blockIdx.x;
    int c = threadIdx.x; // 0..63
    float qx = nodes[3 * i], qy = nodes[3 * i + 1], qz = nodes[3 * i + 2];
    float w0 = Wg[c], w1 = Wg[64 + c], w2 = Wg[128 + c];
    float h = 0.f; // relu >= 0 so max over relu values with init 0 is exact
    #pragma unroll 4
    for (int k = 0; k < K0; ++k) {
        int nb = adj[i * K0 + k];
        float dx = qx - nodes[3 * nb], dy = qy - nodes[3 * nb + 1], dz = qz - nodes[3 * nb + 2];
        float v = dx * w0 + dy * w1 + dz * w2;
        v = v > 0.f ? v : 0.f;
        h = fmaxf(h, v);
    }
    __shared__ float red[64];
    red[c] = h * wg[c];
    __syncthreads();
    for (int s = 32; s > 0; s >>= 1) {
        if (c < s) red[c] += red[c + s];
        __syncthreads();
    }
    if (c == 0) {
        g_keysN[i] = ((unsigned long long)fdesc(red[0]) << 32) | (unsigned)i;
    }
}

// ---------------- generic XOR-bitonic sort (ascending) over u64 keys ----------------
__device__ __forceinline__ unsigned long long* pick(int which) {
    return which ? g_sort : g_keysN;
}

__global__ void k_bitonic_local(int which) {
    __shared__ unsigned long long s[2048];
    unsigned long long* d = pick(which);
    int tid = threadIdx.x;
    int base = blockIdx.x * 2048;
    s[tid] = d[base + tid];
    s[tid + 1024] = d[base + tid + 1024];
    __syncthreads();
    for (int size = 2; size <= 2048; size <<= 1) {
        for (int stride = size >> 1; stride > 0; stride >>= 1) {
            int i = ((tid & ~(stride - 1)) << 1) | (tid & (stride - 1));
            int j = i | stride;
            bool up = (((base + i) & size) == 0);
            unsigned long long a = s[i], b = s[j];
            if ((a > b) == up) { s[i] = b; s[j] = a; }
            __syncthreads();
        }
    }
    d[base + tid] = s[tid];
    d[base + tid + 1024] = s[tid + 1024];
}

__global__ void k_bitonic_global(int which, int size, int stride, int nhalf) {
    unsigned long long* d = pick(which);
    int t = blockIdx.x * blockDim.x + threadIdx.x;
    if (t >= nhalf) return;
    int i = ((t & ~(stride - 1)) << 1) | (t & (stride - 1));
    int j = i | stride;
    bool up = ((i & size) == 0);
    unsigned long long a = d[i], b = d[j];
    if ((a > b) == up) { d[i] = b; d[j] = a; }
}

__global__ void k_bitonic_tail(int which, int size) {
    __shared__ unsigned long long s[2048];
    unsigned long long* d = pick(which);
    int tid = threadIdx.x;
    int base = blockIdx.x * 2048;
    s[tid] = d[base + tid];
    s[tid + 1024] = d[base + tid + 1024];
    __syncthreads();
    bool up = ((base & size) == 0); // size >= 4096 -> uniform per 2048-chunk
    for (int stride = 1024; stride > 0; stride >>= 1) {
        int i = ((tid & ~(stride - 1)) << 1) | (tid & (stride - 1));
        int j = i | stride;
        unsigned long long a = s[i], b = s[j];
        if ((a > b) == up) { s[i] = b; s[j] = a; }
        __syncthreads();
    }
    d[base + tid] = s[tid];
    d[base + tid + 1024] = s[tid + 1024];
}

// ---------------- Stage 2 gather of selected points ----------------
__global__ void k_gather_ext(const float* __restrict__ nodes) {
    int m = blockIdx.x * blockDim.x + threadIdx.x;
    if (m >= MM) return;
    int idx = (int)(unsigned)g_keysN[m];
    g_ext[3 * m]     = nodes[3 * idx];
    g_ext[3 * m + 1] = nodes[3 * idx + 1];
    g_ext[3 * m + 2] = nodes[3 * idx + 2];
}

// ---------------- Stage 3: exact 16-NN (drop self) on 3072 points ----------------
__global__ void k_knn16() {
    __shared__ unsigned long long skey[MM];
    __shared__ unsigned long long red[256];
    __shared__ unsigned long long wl[16];
    int i = blockIdx.x, tid = threadIdx.x;
    float qx = g_ext[3 * i], qy = g_ext[3 * i + 1], qz = g_ext[3 * i + 2];
    for (int j = tid; j < MM; j += 256) {
        float dx = qx - g_ext[3 * j], dy = qy - g_ext[3 * j + 1], dz = qz - g_ext[3 * j + 2];
        float d2 = dx * dx + dy * dy + dz * dz;
        skey[j] = ((unsigned long long)__float_as_uint(d2) << 32) | (unsigned)j;
    }
    __syncthreads();
    for (int r = 0; r < 16; ++r) {
        unsigned long long loc = ~0ULL;
        for (int j = tid; j < MM; j += 256) {
            unsigned long long k = skey[j];
            if (k < loc) loc = k;
        }
        red[tid] = loc;
        __syncthreads();
        for (int s = 128; s > 0; s >>= 1) {
            if (tid < s && red[tid + s] < red[tid]) red[tid] = red[tid + s];
            __syncthreads();
        }
        if (tid == 0) {
            unsigned long long w = red[0];
            wl[r] = w;
            skey[(unsigned)w] = ~0ULL;
        }
        __syncthreads();
    }
    if (tid >= 1 && tid < 16) g_knn[i * KNNK + tid - 1] = (int)(unsigned)wl[tid];
}

// ---------------- Stage 4: DevConv edge feature mean ----------------
__global__ void k_dev(const float* __restrict__ Wd) {
    int i = blockIdx.x, c = threadIdx.x; // 64 threads
    __shared__ float nb[KNNK][3];
    __shared__ float red[64];
    if (c < KNNK * 3) {
        int k = c / 3, d = c % 3;
        nb[k][d] = g_ext[3 * g_knn[i * KNNK + k] + d];
    }
    __syncthreads();
    float qx = g_ext[3 * i], qy = g_ext[3 * i + 1], qz = g_ext[3 * i + 2];
    float w0 = Wd[c], w1 = Wd[64 + c], w2 = Wd[128 + c];
    float m = 0.f;
    #pragma unroll
    for (int k = 0; k < KNNK; ++k) {
        float v = (nb[k][0] - qx) * w0 + (nb[k][1] - qy) * w1 + (nb[k][2] - qz) * w2;
        v = v > 0.f ? v : 0.f;
        m = fmaxf(m, v);
    }
    red[c] = m;
    __syncthreads();
    for (int s = 32; s > 0; s >>= 1) {
        if (c < s) red[c] += red[c + s];
        __syncthreads();
    }
    if (c == 0) g_f[i] = red[0] * (1.f / 64.f);
}

// ---------------- Stage 5: sparse-attention softmax over knn edges ----------------
__global__ void k_soft(const float* __restrict__ a_att) {
    int i = blockIdx.x * blockDim.x + threadIdx.x;
    if (i >= MM) return;
    float a0 = a_att[0], a1 = a_att[1];
    float fi = g_f[i];
    float l[KNNK];
    float mx = -1e30f;
    #pragma unroll
    for (int j = 0; j < KNNK; ++j) {
        l[j] = a0 * fi + a1 * g_f[g_knn[i * KNNK + j]];
        mx = fmaxf(mx, l[j]);
    }
    float s = 0.f;
    #pragma unroll
    for (int j = 0; j < KNNK; ++j) { l[j] = expf(l[j] - mx); s += l[j]; }
    float inv = 1.f / s;
    #pragma unroll
    for (int j = 0; j < KNNK; ++j) g_S[i * KNNK + j] = l[j] * inv;
}

// ---------------- Stage 6/7a: p_init + barycenters ----------------
__global__ void k_tri() {
    int t = blockIdx.x * blockDim.x + threadIdx.x;
    if (t >= NTRI) return;
    int i = t / 14, j = t % 14;
    int a = g_knn[i * KNNK + j], b = g_knn[i * KNNK + j + 1];
    g_p[t] = g_S[i * KNNK + j] * g_S[i * KNNK + j + 1];
    #pragma unroll
    for (int d = 0; d < 3; ++d)
        g_bary[3 * t + d] = (g_ext[3 * i + d] + g_ext[3 * a + d] + g_ext[3 * b + d]) * (1.f / 3.f);
}

__global__ void k_pad() {
    int t = blockIdx.x * blockDim.x + threadIdx.x;
    if (NTRI + t < SORTN) g_sort[NTRI + t] = ~0ULL;
}

// ---------------- Stage 7/8/9 fused: 20-NN over barycenters + MLP score ----------------
__global__ void __launch_bounds__(256)
k_knn20(const float* __restrict__ W1, const float* __restrict__ b1,
        const float* __restrict__ W2) {
    __shared__ float sx[2048], sy[2048], sz[2048];
    __shared__ float w1s[4 * HID], b1s[HID], w2s[HID];
    __shared__ unsigned long long wl[8][KT];
    int tid = threadIdx.x, lane = tid & 31, wid = tid >> 5;
    int q = blockIdx.x * 8 + wid; // grid = NTRI/8 exactly

    for (int t = tid; t < 4 * HID; t += 256) w1s[t] = W1[t];
    if (tid < HID) { b1s[tid] = b1[tid]; w2s[tid] = W2[tid]; }
    if (lane < KT) wl[wid][lane] = ~0ULL;

    float qx = g_bary[3 * q], qy = g_bary[3 * q + 1], qz = g_bary[3 * q + 2];
    unsigned long long thr = ~0ULL;

    for (int tile = 0; tile < NTRI / 2048; ++tile) {
        int base = tile * 2048;
        __syncthreads();
        for (int t = tid; t < 2048; t += 256) {
            int g = base + t;
            sx[t] = g_bary[3 * g];
            sy[t] = g_bary[3 * g + 1];
            sz[t] = g_bary[3 * g + 2];
        }
        __syncthreads();
        for (int s = 0; s < 64; ++s) {
            int c = s * 32 + lane;
            float dx = qx - sx[c], dy = qy - sy[c], dz = qz - sz[c];
            float d2 = dx * dx + dy * dy + dz * dz;
            unsigned long long key =
                ((unsigned long long)__float_as_uint(d2) << 32) | (unsigned)(base + c);
            unsigned mask = __ballot_sync(0xffffffffu, key < thr);
            if (mask) {
                do {
                    int src = __ffs(mask) - 1;
                    mask &= mask - 1;
                    unsigned long long kk = __shfl_sync(0xffffffffu, key, src);
                    if (lane == 0 && kk < wl[wid][KT - 1]) {
                        int p = KT - 1;
                        while (p > 0 && wl[wid][p - 1] > kk) { wl[wid][p] = wl[wid][p - 1]; --p; }
                        wl[wid][p] = kk;
                    }
                } while (mask);
                __syncwarp();
                thr = wl[wid][KT - 1];
            }
        }
    }
    __syncwarp();

    // fused Stage 8+9 MLP over the 20 neighbors (ascending (d2, idx) order == reference order)
    float acc = 0.f;
    for (int j = 0; j < KT; ++j) {
        unsigned long long kk = wl[wid][j];
        int nj = (int)(unsigned)kk;
        float d2 = __uint_as_float((unsigned)(kk >> 32));
        float r3 = sqrtf(d2 + 1e-12f);
        float d0 = g_bary[3 * nj] - qx;
        float d1 = g_bary[3 * nj + 1] - qy;
        float d2v = g_bary[3 * nj + 2] - qz;
        float pj = g_p[nj];
        float part = 0.f;
        #pragma unroll
        for (int u = 0; u < 4; ++u) {
            int k = u * 32 + lane; // conflict-free shared access
            float h = d0 * w1s[k] + d1 * w1s[HID + k] + d2v * w1s[2 * HID + k]
                    + r3 * w1s[3 * HID + k] + b1s[k];
            h = h > 0.f ? h : 0.f;
            part += h * w2s[k];
        }
        acc += part * pj;
    }
    #pragma unroll
    for (int o = 16; o > 0; o >>= 1) acc += __shfl_down_sync(0xffffffffu, acc, o);
    if (lane == 0) {
        float fs = g_p[q] * acc;
        g_sort[q] = ((unsigned long long)fdesc(fs) << 32) | (unsigned)q;
    }
}

// ---------------- Stage 10: output gather ----------------
__global__ void k_out(float* __restrict__ out) {
    int t = blockIdx.x * blockDim.x + threadIdx.x;
    if (t >= TT) return;
    unsigned tri = (unsigned)g_sort[t];
    int i = (int)tri / 14, j = (int)tri % 14;
    int v1 = g_knn[i * KNNK + j], v2 = g_knn[i * KNNK + j + 1];
    #pragma unroll
    for (int d = 0; d < 3; ++d) {
        out[t * 9 + d]     = g_ext[3 * i + d];
        out[t * 9 + 3 + d] = g_ext[3 * v1 + d];
        out[t * 9 + 6 + d] = g_ext[3 * v2 + d];
    }
}

// ---------------- host driver ----------------
static void bitonic_sort(int which, int n) {
    k_bitonic_local<<<n / 2048, 1024>>>(which);
    for (int size = 4096; size <= n; size <<= 1) {
        for (int stride = size >> 1; stride >= 2048; stride >>= 1)
            k_bitonic_global<<<(n / 2 + 255) / 256, 256>>>(which, size, stride, n / 2);
        k_bitonic_tail<<<n / 2048, 1024>>>(which, size);
    }
}

extern "C" void kernel_launch(void* const* d_in, const int* in_sizes, int n_in,
                              void* d_out, int out_size) {
    const float* nodes = (const float*)d_in[0];
    const int*   adj   = (const int*)d_in[1];
    // user_number_triangles may or may not appear as a scalar input; detect via size
    int base = (n_in >= 10 && in_sizes[2] == 1) ? 3 : 2;
    const float* Wg   = (const float*)d_in[base + 0];
    const float* wg   = (const float*)d_in[base + 1];
    const float* Wd   = (const float*)d_in[base + 2];
    const float* aatt = (const float*)d_in[base + 3];
    const float* W1   = (const float*)d_in[base + 4];
    const float* b1   = (const float*)d_in[base + 5];
    const float* W2   = (const float*)d_in[base + 6];
    float* out = (float*)d_out;

    k_gnn<<<NN, 64>>>(nodes, adj, Wg, wg);
    bitonic_sort(0, NN);
    k_gather_ext<<<(MM + 255) / 256, 256>>>(nodes);
    k_knn16<<<MM, 256>>>();
    k_dev<<<MM, 64>>>(Wd);
    k_soft<<<(MM + 255) / 256, 256>>>(aatt);
    k_tri<<<(NTRI + 255) / 256, 256>>>();
    k_pad<<<(SORTN - NTRI + 255) / 256, 256>>>();
    k_knn20<<<NTRI / 8, 256>>>(W1, b1, W2);
    bitonic_sort(1, SORTN);
    k_out<<<(TT + 255) / 256, 256>>>(out);
}

// round 4
// speedup vs baseline: 1.1474x; 1.1474x over previous
#include <cuda_runtime.h>

#define NN    8192
#define K0    16
#define MM    3072
#define KNNK  15
#define TT    1024
#define NTRI  43008      // MM * 14
#define KT    20
#define HID   128
#define SORTN 65536

// ---------------- scratch (static device globals; no allocation) ----------------
__device__ unsigned long long g_keysN[NN];       // stage-2 sort keys
__device__ float              g_ext[MM * 3];     // selected points (AoS xyz)
__device__ float4             g_ext4[MM];        // packed for knn16 tiles
__device__ int                g_knn[MM * KNNK];
__device__ float              g_f[MM];
__device__ float              g_S[MM * KNNK];
__device__ float              g_p[NTRI];
__device__ float4             g_bary4[NTRI];     // xyz + p_init in w
__device__ unsigned long long g_sort[SORTN];     // stage-10 score keys (padded)
__device__ unsigned long long g_topA[32 * 1024]; // merge-prune ping
__device__ unsigned long long g_topB[16 * 1024]; // merge-prune pong

// order-preserving float->u32 map, inverted for DESCENDING sort via ascending keys
__device__ __forceinline__ unsigned fdesc(float v) {
    unsigned fb  = __float_as_uint(v);
    unsigned asc = (fb & 0x80000000u) ? ~fb : (fb | 0x80000000u);
    return ~asc;
}

// ---------------- Stage 1: GNN inclusion scores ----------------
__global__ void k_gnn(const float* __restrict__ nodes, const int* __restrict__ adj,
                      const float* __restrict__ Wg, const float* __restrict__ wg) {
    int i = blockIdx.x;
    int c = threadIdx.x; // 0..63
    float qx = nodes[3 * i], qy = nodes[3 * i + 1], qz = nodes[3 * i + 2];
    float w0 = Wg[c], w1 = Wg[64 + c], w2 = Wg[128 + c];
    float h = 0.f;
    #pragma unroll 4
    for (int k = 0; k < K0; ++k) {
        int nb = adj[i * K0 + k];
        float dx = qx - nodes[3 * nb], dy = qy - nodes[3 * nb + 1], dz = qz - nodes[3 * nb + 2];
        float v = dx * w0 + dy * w1 + dz * w2;
        v = v > 0.f ? v : 0.f;
        h = fmaxf(h, v);
    }
    __shared__ float red[64];
    red[c] = h * wg[c];
    __syncthreads();
    for (int s = 32; s > 0; s >>= 1) {
        if (c < s) red[c] += red[c + s];
        __syncthreads();
    }
    if (c == 0) {
        g_keysN[i] = ((unsigned long long)fdesc(red[0]) << 32) | (unsigned)i;
    }
}

// ---------------- bitonic sort for stage-2 keys (N=8192 only) ----------------
__global__ void k_bitonic_local() {
    __shared__ unsigned long long s[2048];
    int tid = threadIdx.x;
    int base = blockIdx.x * 2048;
    s[tid] = g_keysN[base + tid];
    s[tid + 1024] = g_keysN[base + tid + 1024];
    __syncthreads();
    for (int size = 2; size <= 2048; size <<= 1) {
        for (int stride = size >> 1; stride > 0; stride >>= 1) {
            int i = ((tid & ~(stride - 1)) << 1) | (tid & (stride - 1));
            int j = i | stride;
            bool up = (((base + i) & size) == 0);
            unsigned long long a = s[i], b = s[j];
            if ((a > b) == up) { s[i] = b; s[j] = a; }
            __syncthreads();
        }
    }
    g_keysN[base + tid] = s[tid];
    g_keysN[base + tid + 1024] = s[tid + 1024];
}

__global__ void k_bitonic_global(int size, int stride, int nhalf) {
    int t = blockIdx.x * blockDim.x + threadIdx.x;
    if (t >= nhalf) return;
    int i = ((t & ~(stride - 1)) << 1) | (t & (stride - 1));
    int j = i | stride;
    bool up = ((i & size) == 0);
    unsigned long long a = g_keysN[i], b = g_keysN[j];
    if ((a > b) == up) { g_keysN[i] = b; g_keysN[j] = a; }
}

__global__ void k_bitonic_tail(int size) {
    __shared__ unsigned long long s[2048];
    int tid = threadIdx.x;
    int base = blockIdx.x * 2048;
    s[tid] = g_keysN[base + tid];
    s[tid + 1024] = g_keysN[base + tid + 1024];
    __syncthreads();
    bool up = ((base & size) == 0);
    for (int stride = 1024; stride > 0; stride >>= 1) {
        int i = ((tid & ~(stride - 1)) << 1) | (tid & (stride - 1));
        int j = i | stride;
        unsigned long long a = s[i], b = s[j];
        if ((a > b) == up) { s[i] = b; s[j] = a; }
        __syncthreads();
    }
    g_keysN[base + tid] = s[tid];
    g_keysN[base + tid + 1024] = s[tid + 1024];
}

// ---------------- Stage 2: gather selected points ----------------
__global__ void k_gather_ext(const float* __restrict__ nodes) {
    int m = blockIdx.x * blockDim.x + threadIdx.x;
    if (m >= MM) return;
    int idx = (int)(unsigned)g_keysN[m];
    float x = nodes[3 * idx], y = nodes[3 * idx + 1], z = nodes[3 * idx + 2];
    g_ext[3 * m] = x; g_ext[3 * m + 1] = y; g_ext[3 * m + 2] = z;
    g_ext4[m] = make_float4(x, y, z, 0.f);
}

// ---------------- Stage 3: exact 16-NN, warp-per-query streaming top-16 ----------------
__global__ void __launch_bounds__(256)
k_knn16() {
    __shared__ float4 st[2048];
    __shared__ unsigned long long wl[8][16];
    int tid = threadIdx.x, lane = tid & 31, wid = tid >> 5;
    int q = blockIdx.x * 8 + wid;     // grid = MM/8
    if (lane < 16) wl[wid][lane] = 0x7F800000FFFFFFFFull; // d2=+inf, idx=max

    float qx = g_ext[3 * q], qy = g_ext[3 * q + 1], qz = g_ext[3 * q + 2];
    unsigned long long thr = 0x7F800000FFFFFFFFull;
    float thrd = __uint_as_float((unsigned)(thr >> 32));

    for (int tile = 0; tile < 2; ++tile) {
        int base = tile * 2048;
        int cnt = (tile == 0) ? 2048 : (MM - 2048);
        __syncthreads();
        for (int t = tid; t < cnt; t += 256) st[t] = g_ext4[base + t];
        __syncthreads();
        int iters = cnt >> 5;
        #pragma unroll 4
        for (int s = 0; s < iters; ++s) {
            float4 c = st[(s << 5) | lane];
            float dx = qx - c.x, dy = qy - c.y, dz = qz - c.z;
            float d2 = dx * dx + dy * dy + dz * dz;
            unsigned mask = __ballot_sync(0xffffffffu, d2 <= thrd);
            if (mask) {
                int cbase = base + (s << 5);
                do {
                    int src = __ffs(mask) - 1;
                    mask &= mask - 1;
                    float dd = __shfl_sync(0xffffffffu, d2, src);
                    unsigned long long kk =
                        ((unsigned long long)__float_as_uint(dd) << 32) | (unsigned)(cbase + src);
                    if (lane == 0 && kk < wl[wid][15]) {
                        int p = 15;
                        while (p > 0 && wl[wid][p - 1] > kk) { wl[wid][p] = wl[wid][p - 1]; --p; }
                        wl[wid][p] = kk;
                    }
                } while (mask);
                __syncwarp();
                thr = wl[wid][15];
                thrd = __uint_as_float((unsigned)(thr >> 32));
            }
        }
    }
    __syncwarp();
    if (lane >= 1 && lane < 16)
        g_knn[q * KNNK + lane - 1] = (int)(unsigned)wl[wid][lane]; // drop self (wl[0])
}

// ---------------- Stage 4: DevConv edge feature mean ----------------
__global__ void k_dev(const float* __restrict__ Wd) {
    int i = blockIdx.x, c = threadIdx.x; // 64 threads
    __shared__ float nb[KNNK][3];
    __shared__ float red[64];
    if (c < KNNK * 3) {
        int k = c / 3, d = c % 3;
        nb[k][d] = g_ext[3 * g_knn[i * KNNK + k] + d];
    }
    __syncthreads();
    float qx = g_ext[3 * i], qy = g_ext[3 * i + 1], qz = g_ext[3 * i + 2];
    float w0 = Wd[c], w1 = Wd[64 + c], w2 = Wd[128 + c];
    float m = 0.f;
    #pragma unroll
    for (int k = 0; k < KNNK; ++k) {
        float v = (nb[k][0] - qx) * w0 + (nb[k][1] - qy) * w1 + (nb[k][2] - qz) * w2;
        v = v > 0.f ? v : 0.f;
        m = fmaxf(m, v);
    }
    red[c] = m;
    __syncthreads();
    for (int s = 32; s > 0; s >>= 1) {
        if (c < s) red[c] += red[c + s];
        __syncthreads();
    }
    if (c == 0) g_f[i] = red[0] * (1.f / 64.f);
}

// ---------------- Stage 5: softmax over knn edges ----------------
__global__ void k_soft(const float* __restrict__ a_att) {
    int i = blockIdx.x * blockDim.x + threadIdx.x;
    if (i >= MM) return;
    float a0 = a_att[0], a1 = a_att[1];
    float fi = g_f[i];
    float l[KNNK];
    float mx = -1e30f;
    #pragma unroll
    for (int j = 0; j < KNNK; ++j) {
        l[j] = a0 * fi + a1 * g_f[g_knn[i * KNNK + j]];
        mx = fmaxf(mx, l[j]);
    }
    float s = 0.f;
    #pragma unroll
    for (int j = 0; j < KNNK; ++j) { l[j] = expf(l[j] - mx); s += l[j]; }
    float inv = 1.f / s;
    #pragma unroll
    for (int j = 0; j < KNNK; ++j) g_S[i * KNNK + j] = l[j] * inv;
}

// ---------------- Stage 6/7a: p_init + barycenters (+ sort-key padding) ----------------
__global__ void k_tri() {
    int t = blockIdx.x * blockDim.x + threadIdx.x; // grid covers SORTN
    if (t >= SORTN) return;
    if (t >= NTRI) { g_sort[t] = ~0ULL; return; }
    int i = t / 14, j = t % 14;
    int a = g_knn[i * KNNK + j], b = g_knn[i * KNNK + j + 1];
    float p = g_S[i * KNNK + j] * g_S[i * KNNK + j + 1];
    g_p[t] = p;
    float bx = (g_ext[3 * i] + g_ext[3 * a] + g_ext[3 * b]) * (1.f / 3.f);
    float by = (g_ext[3 * i + 1] + g_ext[3 * a + 1] + g_ext[3 * b + 1]) * (1.f / 3.f);
    float bz = (g_ext[3 * i + 2] + g_ext[3 * a + 2] + g_ext[3 * b + 2]) * (1.f / 3.f);
    g_bary4[t] = make_float4(bx, by, bz, p);
}

// ---------------- Stage 7/8/9 fused: streaming 20-NN + MLP score ----------------
__global__ void __launch_bounds__(512)
k_knn20(const float* __restrict__ W1, const float* __restrict__ b1,
        const float* __restrict__ W2) {
    __shared__ float4 st[2048];
    __shared__ float w1s[4 * HID], b1s[HID], w2s[HID];
    __shared__ unsigned long long wl[16][KT];
    int tid = threadIdx.x, lane = tid & 31, wid = tid >> 5;
    int q = blockIdx.x * 16 + wid;   // grid = NTRI/16

    for (int t = tid; t < 4 * HID; t += 512) w1s[t] = W1[t];
    if (tid < HID) { b1s[tid] = b1[tid]; w2s[tid] = W2[tid]; }
    if (lane < KT) wl[wid][lane] = 0x7F800000FFFFFFFFull;

    float4 qb = g_bary4[q];
    float qx = qb.x, qy = qb.y, qz = qb.z;
    unsigned long long thr = 0x7F800000FFFFFFFFull;
    float thrd = __uint_as_float((unsigned)(thr >> 32));

    for (int tile = 0; tile < NTRI / 2048; ++tile) {
        int base = tile * 2048;
        __syncthreads();
        for (int t = tid; t < 2048; t += 512) st[t] = g_bary4[base + t];
        __syncthreads();
        #pragma unroll 4
        for (int s = 0; s < 64; ++s) {
            float4 c = st[(s << 5) | lane];
            float dx = qx - c.x, dy = qy - c.y, dz = qz - c.z;
            float d2 = dx * dx + dy * dy + dz * dz;
            unsigned mask = __ballot_sync(0xffffffffu, d2 <= thrd);
            if (mask) {
                int cbase = base + (s << 5);
                do {
                    int src = __ffs(mask) - 1;
                    mask &= mask - 1;
                    float dd = __shfl_sync(0xffffffffu, d2, src);
                    unsigned long long kk =
                        ((unsigned long long)__float_as_uint(dd) << 32) | (unsigned)(cbase + src);
                    if (lane == 0 && kk < wl[wid][KT - 1]) {
                        int p = KT - 1;
                        while (p > 0 && wl[wid][p - 1] > kk) { wl[wid][p] = wl[wid][p - 1]; --p; }
                        wl[wid][p] = kk;
                    }
                } while (mask);
                __syncwarp();
                thr = wl[wid][KT - 1];
                thrd = __uint_as_float((unsigned)(thr >> 32));
            }
        }
    }
    __syncwarp();

    // fused Stage 8+9 MLP over the 20 neighbors (ascending (d2, idx) == reference order)
    float acc = 0.f;
    for (int j = 0; j < KT; ++j) {
        unsigned long long kk = wl[wid][j];
        int nj = (int)(unsigned)kk;
        float d2 = __uint_as_float((unsigned)(kk >> 32));
        float r3 = sqrtf(d2 + 1e-12f);
        float4 b4 = g_bary4[nj];
        float d0 = b4.x - qx, d1 = b4.y - qy, d2v = b4.z - qz;
        float pj = b4.w;
        float part = 0.f;
        #pragma unroll
        for (int u = 0; u < 4; ++u) {
            int k = u * 32 + lane; // conflict-free shared access
            float h = d0 * w1s[k] + d1 * w1s[HID + k] + d2v * w1s[2 * HID + k]
                    + r3 * w1s[3 * HID + k] + b1s[k];
            h = h > 0.f ? h : 0.f;
            part += h * w2s[k];
        }
        acc += part * pj;
    }
    #pragma unroll
    for (int o = 16; o > 0; o >>= 1) acc += __shfl_down_sync(0xffffffffu, acc, o);
    if (lane == 0) {
        float fs = g_p[q] * acc;
        g_sort[q] = ((unsigned long long)fdesc(fs) << 32) | (unsigned)q;
    }
}

// ---------------- Stage 10a: per-2048-chunk sort, keep smallest 1024 ----------------
__global__ void __launch_bounds__(1024)
k_sortchunks() {
    __shared__ unsigned long long s[2048];
    int tid = threadIdx.x;
    int base = blockIdx.x * 2048;   // 32 chunks
    s[tid] = g_sort[base + tid];
    s[tid + 1024] = g_sort[base + tid + 1024];
    __syncthreads();
    for (int size = 2; size <= 2048; size <<= 1) {
        for (int stride = size >> 1; stride > 0; stride >>= 1) {
            int i = ((tid & ~(stride - 1)) << 1) | (tid & (stride - 1));
            int j = i | stride;
            bool up = ((i & size) == 0);
            unsigned long long a = s[i], b = s[j];
            if ((a > b) == up) { s[i] = b; s[j] = a; }
            __syncthreads();
        }
    }
    g_topA[blockIdx.x * 1024 + tid] = s[tid]; // smallest 1024, ascending
}

// ---------------- Stage 10b: merge-prune two sorted-1024 lists -> smallest 1024 ----------------
__global__ void __launch_bounds__(1024)
k_merge(int srcA) {
    const unsigned long long* in = srcA ? g_topA : g_topB;
    unsigned long long*       out = srcA ? g_topB : g_topA;
    __shared__ unsigned long long s[2048];
    int tid = threadIdx.x;
    int p = blockIdx.x;
    s[tid] = in[(2 * p) * 1024 + tid];
    s[1024 + tid] = in[(2 * p + 1) * 1024 + (1023 - tid)]; // reversed -> bitonic
    __syncthreads();
    {   // keep min-half
        unsigned long long a = s[tid], b = s[tid + 1024];
        s[tid] = a < b ? a : b;
    }
    __syncthreads();
    for (int stride = 512; stride > 0; stride >>= 1) {
        if (tid < 512) {
            int i = ((tid & ~(stride - 1)) << 1) | (tid & (stride - 1));
            int j = i | stride;
            unsigned long long a = s[i], b = s[j];
            if (a > b) { s[i] = b; s[j] = a; }
        }
        __syncthreads();
    }
    out[p * 1024 + tid] = s[tid];
}

// ---------------- Stage 10c: output gather ----------------
__global__ void k_out(float* __restrict__ out) {
    int t = blockIdx.x * blockDim.x + threadIdx.x;
    if (t >= TT) return;
    unsigned tri = (unsigned)g_topB[t];
    int i = (int)tri / 14, j = (int)tri % 14;
    int v1 = g_knn[i * KNNK + j], v2 = g_knn[i * KNNK + j + 1];
    #pragma unroll
    for (int d = 0; d < 3; ++d) {
        out[t * 9 + d]     = g_ext[3 * i + d];
        out[t * 9 + 3 + d] = g_ext[3 * v1 + d];
        out[t * 9 + 6 + d] = g_ext[3 * v2 + d];
    }
}

// ---------------- host driver ----------------
extern "C" void kernel_launch(void* const* d_in, const int* in_sizes, int n_in,
                              void* d_out, int out_size) {
    const float* nodes = (const float*)d_in[0];
    const int*   adj   = (const int*)d_in[1];
    int base = (n_in >= 10 && in_sizes[2] == 1) ? 3 : 2;
    const float* Wg   = (const float*)d_in[base + 0];
    const float* wg   = (const float*)d_in[base + 1];
    const float* Wd   = (const float*)d_in[base + 2];
    const float* aatt = (const float*)d_in[base + 3];
    const float* W1   = (const float*)d_in[base + 4];
    const float* b1   = (const float*)d_in[base + 5];
    const float* W2   = (const float*)d_in[base + 6];
    float* out = (float*)d_out;

    // Stage 1 + stage-2 sort (N=8192 full bitonic, order must match lax.top_k)
    k_gnn<<<NN, 64>>>(nodes, adj, Wg, wg);
    k_bitonic_local<<<NN / 2048, 1024>>>();
    for (int size = 4096; size <= NN; size <<= 1) {
        for (int stride = size >> 1; stride >= 2048; stride >>= 1)
            k_bitonic_global<<<(NN / 2 + 255) / 256, 256>>>(size, stride, NN / 2);
        k_bitonic_tail<<<NN / 2048, 1024>>>(size);
    }
    k_gather_ext<<<(MM + 255) / 256, 256>>>(nodes);

    k_knn16<<<MM / 8, 256>>>();
    k_dev<<<MM, 64>>>(Wd);
    k_soft<<<(MM + 255) / 256, 256>>>(aatt);
    k_tri<<<SORTN / 256, 256>>>();

    k_knn20<<<NTRI / 16, 512>>>(W1, b1, W2);

    // Stage 10: exact top-1024 via chunk-sort + 5 merge-prune rounds
    k_sortchunks<<<32, 1024>>>();
    k_merge<<<16, 1024>>>(1); // A -> B
    k_merge<<<8, 1024>>>(0);  // B -> A
    k_merge<<<4, 1024>>>(1);  // A -> B
    k_merge<<<2, 1024>>>(0);  // B -> A
    k_merge<<<1, 1024>>>(1);  // A -> B (final sorted 1024 in g_topB)

    k_out<<<(TT + 255) / 256, 256>>>(out);
}

// round 5
// speedup vs baseline: 1.7074x; 1.4881x over previous
#include <cuda_runtime.h>

#define NN    8192
#define K0    16
#define MM    3072
#define KNNK  15
#define TT    1024
#define NTRI  43008      // MM * 14
#define KT    20
#define HID   128
#define SORTN 65536

// ---------------- scratch (static device globals; no allocation) ----------------
__device__ unsigned long long g_keysN[NN];       // stage-2 sort keys
__device__ float              g_ext[MM * 3];     // selected points (AoS xyz)
__device__ float4             g_ext4[MM];        // packed for knn16 tiles
__device__ int                g_knn[MM * KNNK];
__device__ float              g_f[MM];
__device__ float              g_S[MM * KNNK];
__device__ float4             g_bary4[NTRI];     // xyz + p_init in w (for MLP gather)
__device__ unsigned long long g_sort[SORTN];     // stage-10 score keys (padded)
__device__ unsigned long long g_topA[32 * 1024]; // merge-prune ping
__device__ unsigned long long g_topB[16 * 1024]; // merge-prune pong

// order-preserving float->u32 map, inverted for DESCENDING sort via ascending keys
__device__ __forceinline__ unsigned fdesc(float v) {
    unsigned fb  = __float_as_uint(v);
    unsigned asc = (fb & 0x80000000u) ? ~fb : (fb | 0x80000000u);
    return ~asc;
}

// ---------------- Stage 1: GNN inclusion scores ----------------
__global__ void k_gnn(const float* __restrict__ nodes, const int* __restrict__ adj,
                      const float* __restrict__ Wg, const float* __restrict__ wg) {
    int i = blockIdx.x;
    int c = threadIdx.x; // 0..63
    float qx = nodes[3 * i], qy = nodes[3 * i + 1], qz = nodes[3 * i + 2];
    float w0 = Wg[c], w1 = Wg[64 + c], w2 = Wg[128 + c];
    float h = 0.f;
    #pragma unroll 4
    for (int k = 0; k < K0; ++k) {
        int nb = adj[i * K0 + k];
        float dx = qx - nodes[3 * nb], dy = qy - nodes[3 * nb + 1], dz = qz - nodes[3 * nb + 2];
        float v = dx * w0 + dy * w1 + dz * w2;
        v = v > 0.f ? v : 0.f;
        h = fmaxf(h, v);
    }
    __shared__ float red[64];
    red[c] = h * wg[c];
    __syncthreads();
    for (int s = 32; s > 0; s >>= 1) {
        if (c < s) red[c] += red[c + s];
        __syncthreads();
    }
    if (c == 0) {
        g_keysN[i] = ((unsigned long long)fdesc(red[0]) << 32) | (unsigned)i;
    }
}

// ---------------- bitonic sort for stage-2 keys (N=8192 only) ----------------
__global__ void k_bitonic_local() {
    __shared__ unsigned long long s[2048];
    int tid = threadIdx.x;
    int base = blockIdx.x * 2048;
    s[tid] = g_keysN[base + tid];
    s[tid + 1024] = g_keysN[base + tid + 1024];
    __syncthreads();
    for (int size = 2; size <= 2048; size <<= 1) {
        for (int stride = size >> 1; stride > 0; stride >>= 1) {
            int i = ((tid & ~(stride - 1)) << 1) | (tid & (stride - 1));
            int j = i | stride;
            bool up = (((base + i) & size) == 0);
            unsigned long long a = s[i], b = s[j];
            if ((a > b) == up) { s[i] = b; s[j] = a; }
            __syncthreads();
        }
    }
    g_keysN[base + tid] = s[tid];
    g_keysN[base + tid + 1024] = s[tid + 1024];
}

__global__ void k_bitonic_global(int size, int stride, int nhalf) {
    int t = blockIdx.x * blockDim.x + threadIdx.x;
    if (t >= nhalf) return;
    int i = ((t & ~(stride - 1)) << 1) | (t & (stride - 1));
    int j = i | stride;
    bool up = ((i & size) == 0);
    unsigned long long a = g_keysN[i], b = g_keysN[j];
    if ((a > b) == up) { g_keysN[i] = b; g_keysN[j] = a; }
}

__global__ void k_bitonic_tail(int size) {
    __shared__ unsigned long long s[2048];
    int tid = threadIdx.x;
    int base = blockIdx.x * 2048;
    s[tid] = g_keysN[base + tid];
    s[tid + 1024] = g_keysN[base + tid + 1024];
    __syncthreads();
    bool up = ((base & size) == 0);
    for (int stride = 1024; stride > 0; stride >>= 1) {
        int i = ((tid & ~(stride - 1)) << 1) | (tid & (stride - 1));
        int j = i | stride;
        unsigned long long a = s[i], b = s[j];
        if ((a > b) == up) { s[i] = b; s[j] = a; }
        __syncthreads();
    }
    g_keysN[base + tid] = s[tid];
    g_keysN[base + tid + 1024] = s[tid + 1024];
}

// ---------------- Stage 2: gather selected points ----------------
__global__ void k_gather_ext(const float* __restrict__ nodes) {
    int m = blockIdx.x * blockDim.x + threadIdx.x;
    if (m >= MM) return;
    int idx = (int)(unsigned)g_keysN[m];
    float x = nodes[3 * idx], y = nodes[3 * idx + 1], z = nodes[3 * idx + 2];
    g_ext[3 * m] = x; g_ext[3 * m + 1] = y; g_ext[3 * m + 2] = z;
    g_ext4[m] = make_float4(x, y, z, 0.f);
}

// ---------------- Stage 3: exact 16-NN, warp-per-query streaming top-16 ----------------
__global__ void __launch_bounds__(256)
k_knn16() {
    __shared__ float4 st[2048];
    __shared__ unsigned long long wl[8][16];
    int tid = threadIdx.x, lane = tid & 31, wid = tid >> 5;
    int q = blockIdx.x * 8 + wid;     // grid = MM/8
    if (lane < 16) wl[wid][lane] = 0x7F800000FFFFFFFFull; // d2=+inf, idx=max

    float qx = g_ext[3 * q], qy = g_ext[3 * q + 1], qz = g_ext[3 * q + 2];
    unsigned long long thr = 0x7F800000FFFFFFFFull;
    float thrd = __uint_as_float((unsigned)(thr >> 32));

    for (int tile = 0; tile < 2; ++tile) {
        int base = tile * 2048;
        int cnt = (tile == 0) ? 2048 : (MM - 2048);
        __syncthreads();
        for (int t = tid; t < cnt; t += 256) st[t] = g_ext4[base + t];
        __syncthreads();
        int iters = cnt >> 5;
        #pragma unroll 4
        for (int s = 0; s < iters; ++s) {
            float4 c = st[(s << 5) | lane];
            float dx = qx - c.x, dy = qy - c.y, dz = qz - c.z;
            float d2 = dx * dx + dy * dy + dz * dz;
            unsigned mask = __ballot_sync(0xffffffffu, d2 <= thrd);
            if (mask) {
                int cbase = base + (s << 5);
                do {
                    int src = __ffs(mask) - 1;
                    mask &= mask - 1;
                    float dd = __shfl_sync(0xffffffffu, d2, src);
                    unsigned long long kk =
                        ((unsigned long long)__float_as_uint(dd) << 32) | (unsigned)(cbase + src);
                    if (lane == 0 && kk < wl[wid][15]) {
                        int p = 15;
                        while (p > 0 && wl[wid][p - 1] > kk) { wl[wid][p] = wl[wid][p - 1]; --p; }
                        wl[wid][p] = kk;
                    }
                } while (mask);
                __syncwarp();
                thr = wl[wid][15];
                thrd = __uint_as_float((unsigned)(thr >> 32));
            }
        }
    }
    __syncwarp();
    if (lane >= 1 && lane < 16)
        g_knn[q * KNNK + lane - 1] = (int)(unsigned)wl[wid][lane]; // drop self (wl[0])
}

// ---------------- Stage 4: DevConv edge feature mean ----------------
__global__ void k_dev(const float* __restrict__ Wd) {
    int i = blockIdx.x, c = threadIdx.x; // 64 threads
    __shared__ float nb[KNNK][3];
    __shared__ float red[64];
    if (c < KNNK * 3) {
        int k = c / 3, d = c % 3;
        nb[k][d] = g_ext[3 * g_knn[i * KNNK + k] + d];
    }
    __syncthreads();
    float qx = g_ext[3 * i], qy = g_ext[3 * i + 1], qz = g_ext[3 * i + 2];
    float w0 = Wd[c], w1 = Wd[64 + c], w2 = Wd[128 + c];
    float m = 0.f;
    #pragma unroll
    for (int k = 0; k < KNNK; ++k) {
        float v = (nb[k][0] - qx) * w0 + (nb[k][1] - qy) * w1 + (nb[k][2] - qz) * w2;
        v = v > 0.f ? v : 0.f;
        m = fmaxf(m, v);
    }
    red[c] = m;
    __syncthreads();
    for (int s = 32; s > 0; s >>= 1) {
        if (c < s) red[c] += red[c + s];
        __syncthreads();
    }
    if (c == 0) g_f[i] = red[0] * (1.f / 64.f);
}

// ---------------- Stage 5: softmax over knn edges ----------------
__global__ void k_soft(const float* __restrict__ a_att) {
    int i = blockIdx.x * blockDim.x + threadIdx.x;
    if (i >= MM) return;
    float a0 = a_att[0], a1 = a_att[1];
    float fi = g_f[i];
    float l[KNNK];
    float mx = -1e30f;
    #pragma unroll
    for (int j = 0; j < KNNK; ++j) {
        l[j] = a0 * fi + a1 * g_f[g_knn[i * KNNK + j]];
        mx = fmaxf(mx, l[j]);
    }
    float s = 0.f;
    #pragma unroll
    for (int j = 0; j < KNNK; ++j) { l[j] = expf(l[j] - mx); s += l[j]; }
    float inv = 1.f / s;
    #pragma unroll
    for (int j = 0; j < KNNK; ++j) g_S[i * KNNK + j] = l[j] * inv;
}

// ---------------- Stage 6/7a: p_init + barycenters (+ sort-key padding) ----------------
__global__ void k_tri() {
    int t = blockIdx.x * blockDim.x + threadIdx.x; // grid covers SORTN
    if (t >= SORTN) return;
    if (t >= NTRI) { g_sort[t] = ~0ULL; return; }
    int i = t / 14, j = t % 14;
    int a = g_knn[i * KNNK + j], b = g_knn[i * KNNK + j + 1];
    float p = g_S[i * KNNK + j] * g_S[i * KNNK + j + 1];
    float bx = (g_ext[3 * i] + g_ext[3 * a] + g_ext[3 * b]) * (1.f / 3.f);
    float by = (g_ext[3 * i + 1] + g_ext[3 * a + 1] + g_ext[3 * b + 1]) * (1.f / 3.f);
    float bz = (g_ext[3 * i + 2] + g_ext[3 * a + 2] + g_ext[3 * b + 2]) * (1.f / 3.f);
    g_bary4[t] = make_float4(bx, by, bz, p);
}

// ---------------- bitonic flush: sort 64-entry warp area ascending, keep [0..19] ----------------
__device__ __forceinline__ void flush64(unsigned long long* w, int cnt, int lane) {
    // pad unused append slots
    for (int t = 20 + cnt + lane; t < 64; t += 32) w[t] = ~0ULL;
    __syncwarp();
    #pragma unroll
    for (int size = 2; size <= 64; size <<= 1) {
        #pragma unroll
        for (int stride = size >> 1; stride > 0; stride >>= 1) {
            int i = ((lane & ~(stride - 1)) << 1) | (lane & (stride - 1));
            int j = i | stride;
            bool up = ((i & size) == 0);
            unsigned long long a = w[i], b = w[j];
            if ((a > b) == up) { w[i] = b; w[j] = a; }
            __syncwarp();
        }
    }
}

// ---------------- Stage 7/8/9 fused: streaming 20-NN + MLP score ----------------
__global__ void __launch_bounds__(512)
k_knn20(const float* __restrict__ W1, const float* __restrict__ b1,
        const float* __restrict__ W2) {
    __shared__ float sx[2048], sy[2048], sz[2048];
    __shared__ float w1s[4 * HID], b1s[HID], w2s[HID];
    __shared__ unsigned long long wb[16][64];
    int tid = threadIdx.x, lane = tid & 31, wid = tid >> 5;
    int q = blockIdx.x * 16 + wid;   // grid = NTRI/16
    unsigned long long* w = wb[wid];

    for (int t = tid; t < 4 * HID; t += 512) w1s[t] = W1[t];
    if (tid < HID) { b1s[tid] = b1[tid]; w2s[tid] = W2[tid]; }
    if (lane < KT) w[lane] = 0x7F800000FFFFFFFFull; // (d2=+inf, idx=max)

    float4 qb = g_bary4[q];
    float qx = qb.x, qy = qb.y, qz = qb.z;
    float thrd = __uint_as_float(0x7F800000u); // +inf
    int cnt = 0;

    for (int tile = 0; tile < NTRI / 2048; ++tile) {
        int base = tile * 2048;
        __syncthreads();
        for (int t = tid; t < 2048; t += 512) {
            float4 b4 = g_bary4[base + t];
            sx[t] = b4.x; sy[t] = b4.y; sz[t] = b4.z;
        }
        __syncthreads();
        #pragma unroll 4
        for (int s = 0; s < 64; ++s) {
            int c = (s << 5) | lane;
            float dx = qx - sx[c], dy = qy - sy[c], dz = qz - sz[c];
            float d2 = dx * dx + dy * dy + dz * dz;
            bool pass = d2 <= thrd;
            unsigned mask = __ballot_sync(0xffffffffu, pass);
            if (mask) {
                int pop = __popc(mask);
                if (cnt + pop > 44) {      // not enough room: batch-prune first
                    flush64(w, cnt, lane);
                    cnt = 0;
                    thrd = __uint_as_float((unsigned)(w[19] >> 32)); // exact 20th d2
                }
                if (pass) {                // parallel append, no serialization
                    unsigned long long key =
                        ((unsigned long long)__float_as_uint(d2) << 32) | (unsigned)(base + c);
                    w[20 + cnt + __popc(mask & ((1u << lane) - 1u))] = key;
                }
                cnt += pop;
                __syncwarp();
            }
        }
    }
    if (cnt) flush64(w, cnt, lane);
    __syncwarp();

    // fused Stage 8+9 MLP over the 20 neighbors (ascending (d2, idx) == reference order)
    float acc = 0.f;
    for (int j = 0; j < KT; ++j) {
        unsigned long long kk = w[j];
        int nj = (int)(unsigned)kk;
        float d2 = __uint_as_float((unsigned)(kk >> 32));
        float r3 = sqrtf(d2 + 1e-12f);
        float4 b4 = g_bary4[nj];
        float d0 = b4.x - qx, d1 = b4.y - qy, d2v = b4.z - qz;
        float pj = b4.w;
        float part = 0.f;
        #pragma unroll
        for (int u = 0; u < 4; ++u) {
            int k = u * 32 + lane; // conflict-free shared access
            float h = d0 * w1s[k] + d1 * w1s[HID + k] + d2v * w1s[2 * HID + k]
                    + r3 * w1s[3 * HID + k] + b1s[k];
            h = h > 0.f ? h : 0.f;
            part += h * w2s[k];
        }
        acc += part * pj;
    }
    #pragma unroll
    for (int o = 16; o > 0; o >>= 1) acc += __shfl_down_sync(0xffffffffu, acc, o);
    if (lane == 0) {
        float fs = qb.w * acc;
        g_sort[q] = ((unsigned long long)fdesc(fs) << 32) | (unsigned)q;
    }
}

// ---------------- Stage 10a: per-2048-chunk sort, keep smallest 1024 ----------------
__global__ void __launch_bounds__(1024)
k_sortchunks() {
    __shared__ unsigned long long s[2048];
    int tid = threadIdx.x;
    int base = blockIdx.x * 2048;   // 32 chunks
    s[tid] = g_sort[base + tid];
    s[tid + 1024] = g_sort[base + tid + 1024];
    __syncthreads();
    for (int size = 2; size <= 2048; size <<= 1) {
        for (int stride = size >> 1; stride > 0; stride >>= 1) {
            int i = ((tid & ~(stride - 1)) << 1) | (tid & (stride - 1));
            int j = i | stride;
            bool up = ((i & size) == 0);
            unsigned long long a = s[i], b = s[j];
            if ((a > b) == up) { s[i] = b; s[j] = a; }
            __syncthreads();
        }
    }
    g_topA[blockIdx.x * 1024 + tid] = s[tid]; // smallest 1024, ascending
}

// ---------------- Stage 10b: merge-prune two sorted-1024 lists -> smallest 1024 ----------------
__global__ void __launch_bounds__(1024)
k_merge(int srcA) {
    const unsigned long long* in = srcA ? g_topA : g_topB;
    unsigned long long*       out = srcA ? g_topB : g_topA;
    __shared__ unsigned long long s[2048];
    int tid = threadIdx.x;
    int p = blockIdx.x;
    s[tid] = in[(2 * p) * 1024 + tid];
    s[1024 + tid] = in[(2 * p + 1) * 1024 + (1023 - tid)]; // reversed -> bitonic
    __syncthreads();
    {   // keep min-half
        unsigned long long a = s[tid], b = s[tid + 1024];
        s[tid] = a < b ? a : b;
    }
    __syncthreads();
    for (int stride = 512; stride > 0; stride >>= 1) {
        if (tid < 512) {
            int i = ((tid & ~(stride - 1)) << 1) | (tid & (stride - 1));
            int j = i | stride;
            unsigned long long a = s[i], b = s[j];
            if (a > b) { s[i] = b; s[j] = a; }
        }
        __syncthreads();
    }
    out[p * 1024 + tid] = s[tid];
}

// ---------------- Stage 10c: output gather ----------------
__global__ void k_out(float* __restrict__ out) {
    int t = blockIdx.x * blockDim.x + threadIdx.x;
    if (t >= TT) return;
    unsigned tri = (unsigned)g_topB[t];
    int i = (int)tri / 14, j = (int)tri % 14;
    int v1 = g_knn[i * KNNK + j], v2 = g_knn[i * KNNK + j + 1];
    #pragma unroll
    for (int d = 0; d < 3; ++d) {
        out[t * 9 + d]     = g_ext[3 * i + d];
        out[t * 9 + 3 + d] = g_ext[3 * v1 + d];
        out[t * 9 + 6 + d] = g_ext[3 * v2 + d];
    }
}

// ---------------- host driver ----------------
extern "C" void kernel_launch(void* const* d_in, const int* in_sizes, int n_in,
                              void* d_out, int out_size) {
    const float* nodes = (const float*)d_in[0];
    const int*   adj   = (const int*)d_in[1];
    int base = (n_in >= 10 && in_sizes[2] == 1) ? 3 : 2;
    const float* Wg   = (const float*)d_in[base + 0];
    const float* wg   = (const float*)d_in[base + 1];
    const float* Wd   = (const float*)d_in[base + 2];
    const float* aatt = (const float*)d_in[base + 3];
    const float* W1   = (const float*)d_in[base + 4];
    const float* b1   = (const float*)d_in[base + 5];
    const float* W2   = (const float*)d_in[base + 6];
    float* out = (float*)d_out;

    // Stage 1 + stage-2 sort (N=8192 full bitonic, order must match lax.top_k)
    k_gnn<<<NN, 64>>>(nodes, adj, Wg, wg);
    k_bitonic_local<<<NN / 2048, 1024>>>();
    for (int size = 4096; size <= NN; size <<= 1) {
        for (int stride = size >> 1; stride >= 2048; stride >>= 1)
            k_bitonic_global<<<(NN / 2 + 255) / 256, 256>>>(size, stride, NN / 2);
        k_bitonic_tail<<<NN / 2048, 1024>>>(size);
    }
    k_gather_ext<<<(MM + 255) / 256, 256>>>(nodes);

    k_knn16<<<MM / 8, 256>>>();
    k_dev<<<MM, 64>>>(Wd);
    k_soft<<<(MM + 255) / 256, 256>>>(aatt);
    k_tri<<<SORTN / 256, 256>>>();

    k_knn20<<<NTRI / 16, 512>>>(W1, b1, W2);

    // Stage 10: exact top-1024 via chunk-sort + 5 merge-prune rounds
    k_sortchunks<<<32, 1024>>>();
    k_merge<<<16, 1024>>>(1); // A -> B
    k_merge<<<8, 1024>>>(0);  // B -> A
    k_merge<<<4, 1024>>>(1);  // A -> B
    k_merge<<<2, 1024>>>(0);  // B -> A
    k_merge<<<1, 1024>>>(1);  // A -> B (final sorted 1024 in g_topB)

    k_out<<<(TT + 255) / 256, 256>>>(out);
}

// round 8
// speedup vs baseline: 2.2334x; 1.3080x over previous
#include <cuda_runtime.h>

#define NN    8192
#define K0    16
#define MM    3072
#define KNNK  15
#define TT    1024
#define NTRI  43008      // MM * 14
#define KT    20
#define HID   128
#define SORTN 65536
#define QPW   4          // queries per warp in knn20

// ---------------- scratch (static device globals; no allocation) ----------------
__device__ unsigned long long g_keysN[NN];       // stage-2 sort keys
__device__ float              g_ext[MM * 3];     // selected points (AoS xyz)
__device__ float4             g_ext4[MM];        // packed for knn16 tiles
__device__ int                g_knn[MM * KNNK];
__device__ float              g_f[MM];
__device__ float              g_S[MM * KNNK];
__device__ float4             g_bary4[NTRI];     // xyz + p_init in w
__device__ unsigned long long g_sort[SORTN];     // stage-10 score keys (padded)
__device__ unsigned long long g_topA[32 * 1024]; // merge-prune ping
__device__ unsigned long long g_topB[16 * 1024]; // merge-prune pong

// order-preserving float->u32 map, inverted for DESCENDING sort via ascending keys
__device__ __forceinline__ unsigned fdesc(float v) {
    unsigned fb  = __float_as_uint(v);
    unsigned asc = (fb & 0x80000000u) ? ~fb : (fb | 0x80000000u);
    return ~asc;
}

// ---------------- Stage 1: GNN inclusion scores ----------------
__global__ void k_gnn(const float* __restrict__ nodes, const int* __restrict__ adj,
                      const float* __restrict__ Wg, const float* __restrict__ wg) {
    int i = blockIdx.x;
    int c = threadIdx.x; // 0..63
    float qx = nodes[3 * i], qy = nodes[3 * i + 1], qz = nodes[3 * i + 2];
    float w0 = Wg[c], w1 = Wg[64 + c], w2 = Wg[128 + c];
    float h = 0.f;
    #pragma unroll 4
    for (int k = 0; k < K0; ++k) {
        int nb = adj[i * K0 + k];
        float dx = qx - nodes[3 * nb], dy = qy - nodes[3 * nb + 1], dz = qz - nodes[3 * nb + 2];
        float v = dx * w0 + dy * w1 + dz * w2;
        v = v > 0.f ? v : 0.f;
        h = fmaxf(h, v);
    }
    __shared__ float red[64];
    red[c] = h * wg[c];
    __syncthreads();
    for (int s = 32; s > 0; s >>= 1) {
        if (c < s) red[c] += red[c + s];
        __syncthreads();
    }
    if (c == 0) {
        g_keysN[i] = ((unsigned long long)fdesc(red[0]) << 32) | (unsigned)i;
    }
}

// ---------------- bitonic sort for stage-2 keys (N=8192 only) ----------------
__global__ void k_bitonic_local() {
    __shared__ unsigned long long s[2048];
    int tid = threadIdx.x;
    int base = blockIdx.x * 2048;
    s[tid] = g_keysN[base + tid];
    s[tid + 1024] = g_keysN[base + tid + 1024];
    __syncthreads();
    for (int size = 2; size <= 2048; size <<= 1) {
        for (int stride = size >> 1; stride > 0; stride >>= 1) {
            int i = ((tid & ~(stride - 1)) << 1) | (tid & (stride - 1));
            int j = i | stride;
            bool up = (((base + i) & size) == 0);
            unsigned long long a = s[i], b = s[j];
            if ((a > b) == up) { s[i] = b; s[j] = a; }
            __syncthreads();
        }
    }
    g_keysN[base + tid] = s[tid];
    g_keysN[base + tid + 1024] = s[tid + 1024];
}

__global__ void k_bitonic_global(int size, int stride, int nhalf) {
    int t = blockIdx.x * blockDim.x + threadIdx.x;
    if (t >= nhalf) return;
    int i = ((t & ~(stride - 1)) << 1) | (t & (stride - 1));
    int j = i | stride;
    bool up = ((i & size) == 0);
    unsigned long long a = g_keysN[i], b = g_keysN[j];
    if ((a > b) == up) { g_keysN[i] = b; g_keysN[j] = a; }
}

__global__ void k_bitonic_tail(int size) {
    __shared__ unsigned long long s[2048];
    int tid = threadIdx.x;
    int base = blockIdx.x * 2048;
    s[tid] = g_keysN[base + tid];
    s[tid + 1024] = g_keysN[base + tid + 1024];
    __syncthreads();
    bool up = ((base & size) == 0);
    for (int stride = 1024; stride > 0; stride >>= 1) {
        int i = ((tid & ~(stride - 1)) << 1) | (tid & (stride - 1));
        int j = i | stride;
        unsigned long long a = s[i], b = s[j];
        if ((a > b) == up) { s[i] = b; s[j] = a; }
        __syncthreads();
    }
    g_keysN[base + tid] = s[tid];
    g_keysN[base + tid + 1024] = s[tid + 1024];
}

// ---------------- Stage 2: gather selected points ----------------
__global__ void k_gather_ext(const float* __restrict__ nodes) {
    int m = blockIdx.x * blockDim.x + threadIdx.x;
    if (m >= MM) return;
    int idx = (int)(unsigned)g_keysN[m];
    float x = nodes[3 * idx], y = nodes[3 * idx + 1], z = nodes[3 * idx + 2];
    g_ext[3 * m] = x; g_ext[3 * m + 1] = y; g_ext[3 * m + 2] = z;
    g_ext4[m] = make_float4(x, y, z, 0.f);
}

// ---------------- Stage 3: exact 16-NN, warp-per-query streaming top-16 ----------------
__global__ void __launch_bounds__(256)
k_knn16() {
    __shared__ float4 st[2048];
    __shared__ unsigned long long wl[8][16];
    int tid = threadIdx.x, lane = tid & 31, wid = tid >> 5;
    int q = blockIdx.x * 8 + wid;     // grid = MM/8
    if (lane < 16) wl[wid][lane] = 0x7F800000FFFFFFFFull; // d2=+inf, idx=max

    float qx = g_ext[3 * q], qy = g_ext[3 * q + 1], qz = g_ext[3 * q + 2];
    unsigned long long thr = 0x7F800000FFFFFFFFull;
    float thrd = __uint_as_float((unsigned)(thr >> 32));

    for (int tile = 0; tile < 2; ++tile) {
        int base = tile * 2048;
        int cnt = (tile == 0) ? 2048 : (MM - 2048);
        __syncthreads();
        for (int t = tid; t < cnt; t += 256) st[t] = g_ext4[base + t];
        __syncthreads();
        int iters = cnt >> 5;
        #pragma unroll 4
        for (int s = 0; s < iters; ++s) {
            float4 c = st[(s << 5) | lane];
            float dx = qx - c.x, dy = qy - c.y, dz = qz - c.z;
            float d2 = dx * dx + dy * dy + dz * dz;
            unsigned mask = __ballot_sync(0xffffffffu, d2 <= thrd);
            if (mask) {
                int cbase = base + (s << 5);
                do {
                    int src = __ffs(mask) - 1;
                    mask &= mask - 1;
                    float dd = __shfl_sync(0xffffffffu, d2, src);
                    unsigned long long kk =
                        ((unsigned long long)__float_as_uint(dd) << 32) | (unsigned)(cbase + src);
                    if (lane == 0 && kk < wl[wid][15]) {
                        int p = 15;
                        while (p > 0 && wl[wid][p - 1] > kk) { wl[wid][p] = wl[wid][p - 1]; --p; }
                        wl[wid][p] = kk;
                    }
                } while (mask);
                __syncwarp();
                thr = wl[wid][15];
                thrd = __uint_as_float((unsigned)(thr >> 32));
            }
        }
    }
    __syncwarp();
    if (lane >= 1 && lane < 16)
        g_knn[q * KNNK + lane - 1] = (int)(unsigned)wl[wid][lane]; // drop self (wl[0])
}

// ---------------- Stage 4: DevConv edge feature mean ----------------
__global__ void k_dev(const float* __restrict__ Wd) {
    int i = blockIdx.x, c = threadIdx.x; // 64 threads
    __shared__ float nb[KNNK][3];
    __shared__ float red[64];
    if (c < KNNK * 3) {
        int k = c / 3, d = c % 3;
        nb[k][d] = g_ext[3 * g_knn[i * KNNK + k] + d];
    }
    __syncthreads();
    float qx = g_ext[3 * i], qy = g_ext[3 * i + 1], qz = g_ext[3 * i + 2];
    float w0 = Wd[c], w1 = Wd[64 + c], w2 = Wd[128 + c];
    float m = 0.f;
    #pragma unroll
    for (int k = 0; k < KNNK; ++k) {
        float v = (nb[k][0] - qx) * w0 + (nb[k][1] - qy) * w1 + (nb[k][2] - qz) * w2;
        v = v > 0.f ? v : 0.f;
        m = fmaxf(m, v);
    }
    red[c] = m;
    __syncthreads();
    for (int s = 32; s > 0; s >>= 1) {
        if (c < s) red[c] += red[c + s];
        __syncthreads();
    }
    if (c == 0) g_f[i] = red[0] * (1.f / 64.f);
}

// ---------------- Stage 5: softmax over knn edges ----------------
__global__ void k_soft(const float* __restrict__ a_att) {
    int i = blockIdx.x * blockDim.x + threadIdx.x;
    if (i >= MM) return;
    float a0 = a_att[0], a1 = a_att[1];
    float fi = g_f[i];
    float l[KNNK];
    float mx = -1e30f;
    #pragma unroll
    for (int j = 0; j < KNNK; ++j) {
        l[j] = a0 * fi + a1 * g_f[g_knn[i * KNNK + j]];
        mx = fmaxf(mx, l[j]);
    }
    float s = 0.f;
    #pragma unroll
    for (int j = 0; j < KNNK; ++j) { l[j] = expf(l[j] - mx); s += l[j]; }
    float inv = 1.f / s;
    #pragma unroll
    for (int j = 0; j < KNNK; ++j) g_S[i * KNNK + j] = l[j] * inv;
}

// ---------------- Stage 6/7a: p_init + barycenters (+ sort-key padding) ----------------
__global__ void k_tri() {
    int t = blockIdx.x * blockDim.x + threadIdx.x; // grid covers SORTN
    if (t >= SORTN) return;
    if (t >= NTRI) { g_sort[t] = ~0ULL; return; }
    int i = t / 14, j = t % 14;
    int a = g_knn[i * KNNK + j], b = g_knn[i * KNNK + j + 1];
    float p = g_S[i * KNNK + j] * g_S[i * KNNK + j + 1];
    float bx = (g_ext[3 * i] + g_ext[3 * a] + g_ext[3 * b]) * (1.f / 3.f);
    float by = (g_ext[3 * i + 1] + g_ext[3 * a + 1] + g_ext[3 * b + 1]) * (1.f / 3.f);
    float bz = (g_ext[3 * i + 2] + g_ext[3 * a + 2] + g_ext[3 * b + 2]) * (1.f / 3.f);
    g_bary4[t] = make_float4(bx, by, bz, p);
}

// ---------------- bitonic flush: sort 64-entry warp area ascending, keep [0..19] ----------------
__device__ __forceinline__ void flush64(unsigned long long* w, int cnt, int lane) {
    for (int t = 20 + cnt + lane; t < 64; t += 32) w[t] = ~0ULL;
    __syncwarp();
    #pragma unroll
    for (int size = 2; size <= 64; size <<= 1) {
        #pragma unroll
        for (int stride = size >> 1; stride > 0; stride >>= 1) {
            int i = ((lane & ~(stride - 1)) << 1) | (lane & (stride - 1));
            int j = i | stride;
            bool up = ((i & size) == 0);
            unsigned long long a = w[i], b = w[j];
            if ((a > b) == up) { w[i] = b; w[j] = a; }
            __syncwarp();
        }
    }
}

// ---------------- Stage 7/8/9 fused: streaming 20-NN + MLP, 4 queries/warp ----------------
__global__ void __launch_bounds__(256)
k_knn20(const float* __restrict__ W1, const float* __restrict__ b1,
        const float* __restrict__ W2) {
    __shared__ float sx[2048], sy[2048], sz[2048];
    __shared__ float w1s[4 * HID], b1s[HID], w2s[HID];
    __shared__ unsigned long long wb[8][QPW][64];
    int tid = threadIdx.x, lane = tid & 31, wid = tid >> 5;
    int qbase = (blockIdx.x * 8 + wid) * QPW;   // grid = NTRI/(8*QPW)

    for (int t = tid; t < 4 * HID; t += 256) w1s[t] = W1[t];
    if (tid < HID) { b1s[tid] = b1[tid]; w2s[tid] = W2[tid]; }
    if (lane < KT) {
        #pragma unroll
        for (int u = 0; u < QPW; ++u) wb[wid][u][lane] = 0x7F800000FFFFFFFFull;
    }

    float qx[QPW], qy[QPW], qz[QPW], pw[QPW], thr[QPW];
    int cnt[QPW];
    #pragma unroll
    for (int u = 0; u < QPW; ++u) {
        float4 qb = g_bary4[qbase + u];
        qx[u] = qb.x; qy[u] = qb.y; qz[u] = qb.z; pw[u] = qb.w;
        thr[u] = __uint_as_float(0x7F800000u); // +inf
        cnt[u] = 0;
    }

    for (int tile = 0; tile < NTRI / 2048; ++tile) {
        int base = tile * 2048;
        __syncthreads();
        for (int t = tid; t < 2048; t += 256) {
            float4 b4 = g_bary4[base + t];
            sx[t] = b4.x; sy[t] = b4.y; sz[t] = b4.z;
        }
        __syncthreads();
        #pragma unroll 2
        for (int s = 0; s < 64; ++s) {
            int c = (s << 5) | lane;
            float cx = sx[c], cy = sy[c], cz = sz[c];
            float d2v[QPW];
            bool pass[QPW];
            bool any = false;
            #pragma unroll
            for (int u = 0; u < QPW; ++u) {
                float dx = qx[u] - cx, dy = qy[u] - cy, dz = qz[u] - cz;
                d2v[u] = dx * dx + dy * dy + dz * dz;
                pass[u] = d2v[u] <= thr[u];
                any |= pass[u];
            }
            if (__any_sync(0xffffffffu, any)) {
                int cidx = base + (s << 5) + lane;
                #pragma unroll
                for (int u = 0; u < QPW; ++u) {
                    unsigned mu = __ballot_sync(0xffffffffu, pass[u]);
                    if (mu) {
                        int pop = __popc(mu);
                        unsigned long long* w = wb[wid][u];
                        if (cnt[u] + pop > 44) {          // batch-prune first
                            flush64(w, cnt[u], lane);
                            cnt[u] = 0;
                            thr[u] = __uint_as_float((unsigned)(w[19] >> 32)); // exact 20th d2
                        }
                        if (pass[u]) {                    // parallel append
                            unsigned long long key =
                                ((unsigned long long)__float_as_uint(d2v[u]) << 32) | (unsigned)cidx;
                            w[20 + cnt[u] + __popc(mu & ((1u << lane) - 1u))] = key;
                        }
                        cnt[u] += pop;
                    }
                }
                __syncwarp();
            }
        }
    }
    #pragma unroll
    for (int u = 0; u < QPW; ++u)
        if (cnt[u]) flush64(wb[wid][u], cnt[u], lane);
    __syncwarp();

    // fused Stage 8+9 MLP (ascending (d2, idx) == reference order)
    #pragma unroll
    for (int u = 0; u < QPW; ++u) {
        unsigned long long* w = wb[wid][u];
        float acc = 0.f;
        for (int j = 0; j < KT; ++j) {
            unsigned long long kk = w[j];
            int nj = (int)(unsigned)kk;
            float d2 = __uint_as_float((unsigned)(kk >> 32));
            float r3 = sqrtf(d2 + 1e-12f);
            float4 b4 = g_bary4[nj];
            float d0 = b4.x - qx[u], d1 = b4.y - qy[u], d2w = b4.z - qz[u];
            float pj = b4.w;
            float part = 0.f;
            #pragma unroll
            for (int v = 0; v < 4; ++v) {
                int k = v * 32 + lane; // conflict-free shared access
                float h = d0 * w1s[k] + d1 * w1s[HID + k] + d2w * w1s[2 * HID + k]
                        + r3 * w1s[3 * HID + k] + b1s[k];
                h = h > 0.f ? h : 0.f;
                part += h * w2s[k];
            }
            acc += part * pj;
        }
        #pragma unroll
        for (int o = 16; o > 0; o >>= 1) acc += __shfl_down_sync(0xffffffffu, acc, o);
        if (lane == 0) {
            float fs = pw[u] * acc;
            g_sort[qbase + u] = ((unsigned long long)fdesc(fs) << 32) | (unsigned)(qbase + u);
        }
    }
}

// ---------------- Stage 10a: per-2048-chunk sort, keep smallest 1024 ----------------
__global__ void __launch_bounds__(1024)
k_sortchunks() {
    __shared__ unsigned long long s[2048];
    int tid = threadIdx.x;
    int base = blockIdx.x * 2048;   // 32 chunks
    s[tid] = g_sort[base + tid];
    s[tid + 1024] = g_sort[base + tid + 1024];
    __syncthreads();
    for (int size = 2; size <= 2048; size <<= 1) {
        for (int stride = size >> 1; stride > 0; stride >>= 1) {
            int i = ((tid & ~(stride - 1)) << 1) | (tid & (stride - 1));
            int j = i | stride;
            bool up = ((i & size) == 0);
            unsigned long long a = s[i], b = s[j];
            if ((a > b) == up) { s[i] = b; s[j] = a; }
            __syncthreads();
        }
    }
    g_topA[blockIdx.x * 1024 + tid] = s[tid]; // smallest 1024, ascending
}

// ---------------- Stage 10b: merge-prune two sorted-1024 lists -> smallest 1024 ----------------
__global__ void __launch_bounds__(1024)
k_merge(int srcA) {
    const unsigned long long* in = srcA ? g_topA : g_topB;
    unsigned long long*       out = srcA ? g_topB : g_topA;
    __shared__ unsigned long long s[2048];
    int tid = threadIdx.x;
    int p = blockIdx.x;
    s[tid] = in[(2 * p) * 1024 + tid];
    s[1024 + tid] = in[(2 * p + 1) * 1024 + (1023 - tid)]; // reversed -> bitonic
    __syncthreads();
    {   // keep min-half
        unsigned long long a = s[tid], b = s[tid + 1024];
        s[tid] = a < b ? a : b;
    }
    __syncthreads();
    for (int stride = 512; stride > 0; stride >>= 1) {
        if (tid < 512) {
            int i = ((tid & ~(stride - 1)) << 1) | (tid & (stride - 1));
            int j = i | stride;
            unsigned long long a = s[i], b = s[j];
            if (a > b) { s[i] = b; s[j] = a; }
        }
        __syncthreads();
    }
    out[p * 1024 + tid] = s[tid];
}

// ---------------- Stage 10c: output gather ----------------
__global__ void k_out(float* __restrict__ out) {
    int t = blockIdx.x * blockDim.x + threadIdx.x;
    if (t >= TT) return;
    unsigned tri = (unsigned)g_topB[t];
    int i = (int)tri / 14, j = (int)tri % 14;
    int v1 = g_knn[i * KNNK + j], v2 = g_knn[i * KNNK + j + 1];
    #pragma unroll
    for (int d = 0; d < 3; ++d) {
        out[t * 9 + d]     = g_ext[3 * i + d];
        out[t * 9 + 3 + d] = g_ext[3 * v1 + d];
        out[t * 9 + 6 + d] = g_ext[3 * v2 + d];
    }
}

// ---------------- host driver ----------------
extern "C" void kernel_launch(void* const* d_in, const int* in_sizes, int n_in,
                              void* d_out, int out_size) {
    const float* nodes = (const float*)d_in[0];
    const int*   adj   = (const int*)d_in[1];
    int base = (n_in >= 10 && in_sizes[2] == 1) ? 3 : 2;
    const float* Wg   = (const float*)d_in[base + 0];
    const float* wg   = (const float*)d_in[base + 1];
    const float* Wd   = (const float*)d_in[base + 2];
    const float* aatt = (const float*)d_in[base + 3];
    const float* W1   = (const float*)d_in[base + 4];
    const float* b1   = (const float*)d_in[base + 5];
    const float* W2   = (const float*)d_in[base + 6];
    float* out = (float*)d_out;

    // Stage 1 + stage-2 sort (N=8192 full bitonic, order must match lax.top_k)
    k_gnn<<<NN, 64>>>(nodes, adj, Wg, wg);
    k_bitonic_local<<<NN / 2048, 1024>>>();
    for (int size = 4096; size <= NN; size <<= 1) {
        for (int stride = size >> 1; stride >= 2048; stride >>= 1)
            k_bitonic_global<<<(NN / 2 + 255) / 256, 256>>>(size, stride, NN / 2);
        k_bitonic_tail<<<NN / 2048, 1024>>>(size);
    }
    k_gather_ext<<<(MM + 255) / 256, 256>>>(nodes);

    k_knn16<<<MM / 8, 256>>>();
    k_dev<<<MM, 64>>>(Wd);
    k_soft<<<(MM + 255) / 256, 256>>>(aatt);
    k_tri<<<SORTN / 256, 256>>>();

    k_knn20<<<NTRI / (8 * QPW), 256>>>(W1, b1, W2);

    // Stage 10: exact top-1024 via chunk-sort + 5 merge-prune rounds
    k_sortchunks<<<32, 1024>>>();
    k_merge<<<16, 1024>>>(1); // A -> B
    k_merge<<<8, 1024>>>(0);  // B -> A
    k_merge<<<4, 1024>>>(1);  // A -> B
    k_merge<<<2, 1024>>>(0);  // B -> A
    k_merge<<<1, 1024>>>(1);  // A -> B (final sorted 1024 in g_topB)

    k_out<<<(TT + 255) / 256, 256>>>(out);
}

// round 9
// speedup vs baseline: 3.1558x; 1.4130x over previous
#include <cuda_runtime.h>

#define NN    8192
#define K0    16
#define MM    3072
#define KNNK  15
#define TT    1024
#define NTRI  43008      // MM * 14 = 21 * 2048
#define KT    20
#define HID   128
#define SORTN 65536
#define QPW   4          // queries per warp in knn20
#define NCELL 4096       // 16^3 morton cells
#define NTILE 21         // NTRI / 2048

// ---------------- scratch (static device globals; no allocation) ----------------
__device__ unsigned long long g_keysN[NN];       // stage-2 sort keys
__device__ float              g_ext[MM * 3];     // selected points (AoS xyz)
__device__ float4             g_ext4[MM];        // packed for knn16 tiles
__device__ int                g_knn[MM * KNNK];
__device__ float              g_f[MM];
__device__ float              g_S[MM * KNNK];
__device__ float4             g_bary4[NTRI];     // xyz + p_init in w (ORIGINAL order)
__device__ float4             g_bary4p[NTRI];    // spatially permuted
__device__ int                g_oidx[NTRI];      // permuted pos -> original idx
__device__ unsigned           g_bb[6];           // enc-mapped global bbox lo xyz, hi xyz
__device__ int                g_cellcnt[NCELL];
__device__ int                g_celloff[NCELL];
__device__ float              g_tilebb[NTILE][6];
__device__ unsigned long long g_sort[SORTN];     // stage-10 score keys (padded)
__device__ unsigned long long g_topA[32 * 1024]; // merge-prune ping
__device__ unsigned long long g_topB[16 * 1024]; // merge-prune pong

// order-preserving float->u32 map, inverted for DESCENDING sort via ascending keys
__device__ __forceinline__ unsigned fdesc(float v) {
    unsigned fb  = __float_as_uint(v);
    unsigned asc = (fb & 0x80000000u) ? ~fb : (fb | 0x80000000u);
    return ~asc;
}
// monotone-ascending float<->u32 maps (for atomic min/max bbox)
__device__ __forceinline__ unsigned fenc(float v) {
    unsigned u = __float_as_uint(v);
    return (u & 0x80000000u) ? ~u : (u | 0x80000000u);
}
__device__ __forceinline__ float fdec(unsigned u) {
    return (u & 0x80000000u) ? __uint_as_float(u ^ 0x80000000u) : __uint_as_float(~u);
}

// ---------------- Stage 1: GNN inclusion scores ----------------
__global__ void k_gnn(const float* __restrict__ nodes, const int* __restrict__ adj,
                      const float* __restrict__ Wg, const float* __restrict__ wg) {
    int i = blockIdx.x;
    int c = threadIdx.x; // 0..63
    float qx = nodes[3 * i], qy = nodes[3 * i + 1], qz = nodes[3 * i + 2];
    float w0 = Wg[c], w1 = Wg[64 + c], w2 = Wg[128 + c];
    float h = 0.f;
    #pragma unroll 4
    for (int k = 0; k < K0; ++k) {
        int nb = adj[i * K0 + k];
        float dx = qx - nodes[3 * nb], dy = qy - nodes[3 * nb + 1], dz = qz - nodes[3 * nb + 2];
        float v = dx * w0 + dy * w1 + dz * w2;
        v = v > 0.f ? v : 0.f;
        h = fmaxf(h, v);
    }
    __shared__ float red[64];
    red[c] = h * wg[c];
    __syncthreads();
    for (int s = 32; s > 0; s >>= 1) {
        if (c < s) red[c] += red[c + s];
        __syncthreads();
    }
    if (c == 0) {
        g_keysN[i] = ((unsigned long long)fdesc(red[0]) << 32) | (unsigned)i;
    }
}

// ---------------- bitonic sort for stage-2 keys (N=8192 only) ----------------
__global__ void k_bitonic_local() {
    __shared__ unsigned long long s[2048];
    int tid = threadIdx.x;
    int base = blockIdx.x * 2048;
    s[tid] = g_keysN[base + tid];
    s[tid + 1024] = g_keysN[base + tid + 1024];
    __syncthreads();
    for (int size = 2; size <= 2048; size <<= 1) {
        for (int stride = size >> 1; stride > 0; stride >>= 1) {
            int i = ((tid & ~(stride - 1)) << 1) | (tid & (stride - 1));
            int j = i | stride;
            bool up = (((base + i) & size) == 0);
            unsigned long long a = s[i], b = s[j];
            if ((a > b) == up) { s[i] = b; s[j] = a; }
            __syncthreads();
        }
    }
    g_keysN[base + tid] = s[tid];
    g_keysN[base + tid + 1024] = s[tid + 1024];
}

__global__ void k_bitonic_global(int size, int stride, int nhalf) {
    int t = blockIdx.x * blockDim.x + threadIdx.x;
    if (t >= nhalf) return;
    int i = ((t & ~(stride - 1)) << 1) | (t & (stride - 1));
    int j = i | stride;
    bool up = ((i & size) == 0);
    unsigned long long a = g_keysN[i], b = g_keysN[j];
    if ((a > b) == up) { g_keysN[i] = b; g_keysN[j] = a; }
}

__global__ void k_bitonic_tail(int size) {
    __shared__ unsigned long long s[2048];
    int tid = threadIdx.x;
    int base = blockIdx.x * 2048;
    s[tid] = g_keysN[base + tid];
    s[tid + 1024] = g_keysN[base + tid + 1024];
    __syncthreads();
    bool up = ((base & size) == 0);
    for (int stride = 1024; stride > 0; stride >>= 1) {
        int i = ((tid & ~(stride - 1)) << 1) | (tid & (stride - 1));
        int j = i | stride;
        unsigned long long a = s[i], b = s[j];
        if ((a > b) == up) { s[i] = b; s[j] = a; }
        __syncthreads();
    }
    g_keysN[base + tid] = s[tid];
    g_keysN[base + tid + 1024] = s[tid + 1024];
}

// ---------------- Stage 2: gather selected points ----------------
__global__ void k_gather_ext(const float* __restrict__ nodes) {
    int m = blockIdx.x * blockDim.x + threadIdx.x;
    if (m >= MM) return;
    int idx = (int)(unsigned)g_keysN[m];
    float x = nodes[3 * idx], y = nodes[3 * idx + 1], z = nodes[3 * idx + 2];
    g_ext[3 * m] = x; g_ext[3 * m + 1] = y; g_ext[3 * m + 2] = z;
    g_ext4[m] = make_float4(x, y, z, 0.f);
}

// ---------------- Stage 3: exact 16-NN, warp-per-query streaming top-16 ----------------
__global__ void __launch_bounds__(256)
k_knn16() {
    __shared__ float4 st[2048];
    __shared__ unsigned long long wl[8][16];
    int tid = threadIdx.x, lane = tid & 31, wid = tid >> 5;
    int q = blockIdx.x * 8 + wid;     // grid = MM/8
    if (lane < 16) wl[wid][lane] = 0x7F800000FFFFFFFFull; // d2=+inf, idx=max

    float qx = g_ext[3 * q], qy = g_ext[3 * q + 1], qz = g_ext[3 * q + 2];
    unsigned long long thr = 0x7F800000FFFFFFFFull;
    float thrd = __uint_as_float((unsigned)(thr >> 32));

    for (int tile = 0; tile < 2; ++tile) {
        int base = tile * 2048;
        int cnt = (tile == 0) ? 2048 : (MM - 2048);
        __syncthreads();
        for (int t = tid; t < cnt; t += 256) st[t] = g_ext4[base + t];
        __syncthreads();
        int iters = cnt >> 5;
        #pragma unroll 4
        for (int s = 0; s < iters; ++s) {
            float4 c = st[(s << 5) | lane];
            float dx = qx - c.x, dy = qy - c.y, dz = qz - c.z;
            float d2 = dx * dx + dy * dy + dz * dz;
            unsigned mask = __ballot_sync(0xffffffffu, d2 <= thrd);
            if (mask) {
                int cbase = base + (s << 5);
                do {
                    int src = __ffs(mask) - 1;
                    mask &= mask - 1;
                    float dd = __shfl_sync(0xffffffffu, d2, src);
                    unsigned long long kk =
                        ((unsigned long long)__float_as_uint(dd) << 32) | (unsigned)(cbase + src);
                    if (lane == 0 && kk < wl[wid][15]) {
                        int p = 15;
                        while (p > 0 && wl[wid][p - 1] > kk) { wl[wid][p] = wl[wid][p - 1]; --p; }
                        wl[wid][p] = kk;
                    }
                } while (mask);
                __syncwarp();
                thr = wl[wid][15];
                thrd = __uint_as_float((unsigned)(thr >> 32));
            }
        }
    }
    __syncwarp();
    if (lane >= 1 && lane < 16)
        g_knn[q * KNNK + lane - 1] = (int)(unsigned)wl[wid][lane]; // drop self (wl[0])
}

// ---------------- Stage 4: DevConv edge feature mean ----------------
__global__ void k_dev(const float* __restrict__ Wd) {
    int i = blockIdx.x, c = threadIdx.x; // 64 threads
    __shared__ float nb[KNNK][3];
    __shared__ float red[64];
    if (c < KNNK * 3) {
        int k = c / 3, d = c % 3;
        nb[k][d] = g_ext[3 * g_knn[i * KNNK + k] + d];
    }
    __syncthreads();
    float qx = g_ext[3 * i], qy = g_ext[3 * i + 1], qz = g_ext[3 * i + 2];
    float w0 = Wd[c], w1 = Wd[64 + c], w2 = Wd[128 + c];
    float m = 0.f;
    #pragma unroll
    for (int k = 0; k < KNNK; ++k) {
        float v = (nb[k][0] - qx) * w0 + (nb[k][1] - qy) * w1 + (nb[k][2] - qz) * w2;
        v = v > 0.f ? v : 0.f;
        m = fmaxf(m, v);
    }
    red[c] = m;
    __syncthreads();
    for (int s = 32; s > 0; s >>= 1) {
        if (c < s) red[c] += red[c + s];
        __syncthreads();
    }
    if (c == 0) g_f[i] = red[0] * (1.f / 64.f);
}

// ---------------- Stage 5: softmax over knn edges ----------------
__global__ void k_soft(const float* __restrict__ a_att) {
    int i = blockIdx.x * blockDim.x + threadIdx.x;
    if (i >= MM) return;
    float a0 = a_att[0], a1 = a_att[1];
    float fi = g_f[i];
    float l[KNNK];
    float mx = -1e30f;
    #pragma unroll
    for (int j = 0; j < KNNK; ++j) {
        l[j] = a0 * fi + a1 * g_f[g_knn[i * KNNK + j]];
        mx = fmaxf(mx, l[j]);
    }
    float s = 0.f;
    #pragma unroll
    for (int j = 0; j < KNNK; ++j) { l[j] = expf(l[j] - mx); s += l[j]; }
    float inv = 1.f / s;
    #pragma unroll
    for (int j = 0; j < KNNK; ++j) g_S[i * KNNK + j] = l[j] * inv;
}

// ---------------- init: zero cell counters + bbox accumulators ----------------
__global__ void k_init() {
    int t = blockIdx.x * blockDim.x + threadIdx.x;
    if (t < NCELL) g_cellcnt[t] = 0;
    if (t < 3) g_bb[t] = 0xFFFFFFFFu;
    else if (t < 6) g_bb[t] = 0u;
}

// ---------------- Stage 6/7a: p_init + barycenters + pad + bbox reduce ----------------
__global__ void k_tri() {
    __shared__ unsigned sbb[6];
    if (threadIdx.x < 3) sbb[threadIdx.x] = 0xFFFFFFFFu;
    else if (threadIdx.x < 6) sbb[threadIdx.x] = 0u;
    __syncthreads();
    int t = blockIdx.x * blockDim.x + threadIdx.x; // grid covers SORTN
    if (t < SORTN && t >= NTRI) g_sort[t] = ~0ULL;
    if (t < NTRI) {
        int i = t / 14, j = t % 14;
        int a = g_knn[i * KNNK + j], b = g_knn[i * KNNK + j + 1];
        float p = g_S[i * KNNK + j] * g_S[i * KNNK + j + 1];
        float bx = (g_ext[3 * i] + g_ext[3 * a] + g_ext[3 * b]) * (1.f / 3.f);
        float by = (g_ext[3 * i + 1] + g_ext[3 * a + 1] + g_ext[3 * b + 1]) * (1.f / 3.f);
        float bz = (g_ext[3 * i + 2] + g_ext[3 * a + 2] + g_ext[3 * b + 2]) * (1.f / 3.f);
        g_bary4[t] = make_float4(bx, by, bz, p);
        atomicMin(&sbb[0], fenc(bx)); atomicMin(&sbb[1], fenc(by)); atomicMin(&sbb[2], fenc(bz));
        atomicMax(&sbb[3], fenc(bx)); atomicMax(&sbb[4], fenc(by)); atomicMax(&sbb[5], fenc(bz));
    }
    __syncthreads();
    if (threadIdx.x < 3) atomicMin(&g_bb[threadIdx.x], sbb[threadIdx.x]);
    else if (threadIdx.x < 6) atomicMax(&g_bb[threadIdx.x], sbb[threadIdx.x]);
}

// ---------------- morton cell id (16^3) ----------------
__device__ __forceinline__ int cellof(float x, float y, float z) {
    float lox = fdec(g_bb[0]), loy = fdec(g_bb[1]), loz = fdec(g_bb[2]);
    float hix = fdec(g_bb[3]), hiy = fdec(g_bb[4]), hiz = fdec(g_bb[5]);
    int cx = (int)((x - lox) / (hix - lox) * 16.f);
    int cy = (int)((y - loy) / (hiy - loy) * 16.f);
    int cz = (int)((z - loz) / (hiz - loz) * 16.f);
    cx = min(max(cx, 0), 15); cy = min(max(cy, 0), 15); cz = min(max(cz, 0), 15);
    int cell = 0;
    #pragma unroll
    for (int i = 0; i < 4; ++i) {
        cell |= (((cx >> i) & 1) << (3 * i + 2)) | (((cy >> i) & 1) << (3 * i + 1))
              | (((cz >> i) & 1) << (3 * i));
    }
    return cell;
}

__global__ void k_cellcount() {
    int t = blockIdx.x * blockDim.x + threadIdx.x;
    if (t >= NTRI) return;
    float4 b4 = g_bary4[t];
    atomicAdd(&g_cellcnt[cellof(b4.x, b4.y, b4.z)], 1);
}

// exclusive prefix over 4096 cells; single block of 1024 threads, 4 cells each
__global__ void __launch_bounds__(1024)
k_prefix() {
    __shared__ int s[1024];
    int tid = threadIdx.x;
    int c0 = g_cellcnt[4 * tid], c1 = g_cellcnt[4 * tid + 1];
    int c2 = g_cellcnt[4 * tid + 2], c3 = g_cellcnt[4 * tid + 3];
    int sum = c0 + c1 + c2 + c3;
    s[tid] = sum;
    __syncthreads();
    for (int off = 1; off < 1024; off <<= 1) {
        int v = s[tid];
        if (tid >= off) v += s[tid - off];
        __syncthreads();
        s[tid] = v;
        __syncthreads();
    }
    int base = s[tid] - sum; // exclusive
    g_celloff[4 * tid] = base;
    g_celloff[4 * tid + 1] = base + c0;
    g_celloff[4 * tid + 2] = base + c0 + c1;
    g_celloff[4 * tid + 3] = base + c0 + c1 + c2;
}

__global__ void k_scatter() {
    int t = blockIdx.x * blockDim.x + threadIdx.x;
    if (t >= NTRI) return;
    float4 b4 = g_bary4[t];
    int pos = atomicAdd(&g_celloff[cellof(b4.x, b4.y, b4.z)], 1);
    g_bary4p[pos] = b4;
    g_oidx[pos] = t;
}

// per-2048-tile bbox over the permuted array (one block per tile)
__global__ void __launch_bounds__(256)
k_tilebbox() {
    __shared__ unsigned sbb[6];
    if (threadIdx.x < 3) sbb[threadIdx.x] = 0xFFFFFFFFu;
    else if (threadIdx.x < 6) sbb[threadIdx.x] = 0u;
    __syncthreads();
    int base = blockIdx.x * 2048;
    for (int i = threadIdx.x; i < 2048; i += 256) {
        float4 b4 = g_bary4p[base + i];
        atomicMin(&sbb[0], fenc(b4.x)); atomicMin(&sbb[1], fenc(b4.y)); atomicMin(&sbb[2], fenc(b4.z));
        atomicMax(&sbb[3], fenc(b4.x)); atomicMax(&sbb[4], fenc(b4.y)); atomicMax(&sbb[5], fenc(b4.z));
    }
    __syncthreads();
    if (threadIdx.x < 6) g_tilebb[blockIdx.x][threadIdx.x] = fdec(sbb[threadIdx.x]);
}

// ---------------- bitonic flush: sort 64-entry warp area ascending, keep [0..19] ----------------
__device__ __forceinline__ void flush64(unsigned long long* w, int cnt, int lane) {
    for (int t = 20 + cnt + lane; t < 64; t += 32) w[t] = ~0ULL;
    __syncwarp();
    #pragma unroll
    for (int size = 2; size <= 64; size <<= 1) {
        #pragma unroll
        for (int stride = size >> 1; stride > 0; stride >>= 1) {
            int i = ((lane & ~(stride - 1)) << 1) | (lane & (stride - 1));
            int j = i | stride;
            bool up = ((i & size) == 0);
            unsigned long long a = w[i], b = w[j];
            if ((a > b) == up) { w[i] = b; w[j] = a; }
            __syncwarp();
        }
    }
}

// ---------------- Stage 7/8/9 fused: pruned streaming 20-NN + MLP, 4 queries/warp ----------------
__global__ void __launch_bounds__(256)
k_knn20(const float* __restrict__ W1, const float* __restrict__ b1,
        const float* __restrict__ W2) {
    __shared__ float sx[2048], sy[2048], sz[2048];
    __shared__ int so[2048];
    __shared__ float w1s[4 * HID], b1s[HID], w2s[HID];
    __shared__ unsigned long long wb[8][QPW][64];
    __shared__ int needs[8];
    int tid = threadIdx.x, lane = tid & 31, wid = tid >> 5;
    int pbase = (blockIdx.x * 8 + wid) * QPW;   // PERMUTED query positions
    int home = (blockIdx.x * 32) >> 11;         // tile containing this block's queries

    for (int t = tid; t < 4 * HID; t += 256) w1s[t] = W1[t];
    if (tid < HID) { b1s[tid] = b1[tid]; w2s[tid] = W2[tid]; }
    if (lane < KT) {
        #pragma unroll
        for (int u = 0; u < QPW; ++u) wb[wid][u][lane] = 0x7F800000FFFFFFFFull;
    }

    float qx[QPW], qy[QPW], qz[QPW], pw[QPW], thr[QPW];
    int qo[QPW], cnt[QPW];
    #pragma unroll
    for (int u = 0; u < QPW; ++u) {
        float4 qb = g_bary4p[pbase + u];
        qx[u] = qb.x; qy[u] = qb.y; qz[u] = qb.z; pw[u] = qb.w;
        qo[u] = g_oidx[pbase + u];
        thr[u] = __uint_as_float(0x7F800000u); // +inf
        cnt[u] = 0;
    }

    for (int tt = 0; tt < NTILE; ++tt) {
        int tile = home + tt; if (tile >= NTILE) tile -= NTILE;
        // exact bbox prune: skip tile iff minD2 > thr for all queries of this warp
        float lx = g_tilebb[tile][0], ly = g_tilebb[tile][1], lz = g_tilebb[tile][2];
        float hx = g_tilebb[tile][3], hy = g_tilebb[tile][4], hz = g_tilebb[tile][5];
        bool wneed = false;
        #pragma unroll
        for (int u = 0; u < QPW; ++u) {
            float ddx = fmaxf(fmaxf(lx - qx[u], qx[u] - hx), 0.f);
            float ddy = fmaxf(fmaxf(ly - qy[u], qy[u] - hy), 0.f);
            float ddz = fmaxf(fmaxf(lz - qz[u], qz[u] - hz), 0.f);
            wneed |= (ddx * ddx + ddy * ddy + ddz * ddz) <= thr[u];
        }
        if (lane == 0) needs[wid] = wneed;
        __syncthreads();   // needs visible; also: all warps done with previous tile buffer
        bool anyneed = false;
        #pragma unroll
        for (int wv = 0; wv < 8; ++wv) anyneed |= (needs[wv] != 0);
        if (!anyneed) continue;    // uniform across block

        int base = tile * 2048;
        for (int t = tid; t < 2048; t += 256) {
            float4 b4 = g_bary4p[base + t];
            sx[t] = b4.x; sy[t] = b4.y; sz[t] = b4.z;
            so[t] = g_oidx[base + t];
        }
        __syncthreads();

        if (wneed) {
            #pragma unroll 2
            for (int s = 0; s < 64; ++s) {
                int c = (s << 5) | lane;
                float cx = sx[c], cy = sy[c], cz = sz[c];
                float d2v[QPW];
                bool pass[QPW];
                bool any = false;
                #pragma unroll
                for (int u = 0; u < QPW; ++u) {
                    float dx = qx[u] - cx, dy = qy[u] - cy, dz = qz[u] - cz;
                    d2v[u] = dx * dx + dy * dy + dz * dz;
                    pass[u] = d2v[u] <= thr[u];
                    any |= pass[u];
                }
                if (__any_sync(0xffffffffu, any)) {
                    int oi = so[c];      // ORIGINAL candidate index (exact tie-break)
                    #pragma unroll
                    for (int u = 0; u < QPW; ++u) {
                        unsigned mu = __ballot_sync(0xffffffffu, pass[u]);
                        if (mu) {
                            int pop = __popc(mu);
                            unsigned long long* w = wb[wid][u];
                            if (cnt[u] + pop > 44) {          // batch-prune first
                                flush64(w, cnt[u], lane);
                                cnt[u] = 0;
                                thr[u] = __uint_as_float((unsigned)(w[19] >> 32)); // exact 20th d2
                            }
                            if (pass[u]) {                    // parallel append
                                unsigned long long key =
                                    ((unsigned long long)__float_as_uint(d2v[u]) << 32) | (unsigned)oi;
                                w[20 + cnt[u] + __popc(mu & ((1u << lane) - 1u))] = key;
                            }
                            cnt[u] += pop;
                        }
                    }
                    __syncwarp();
                }
            }
        }
    }
    #pragma unroll
    for (int u = 0; u < QPW; ++u)
        if (cnt[u]) flush64(wb[wid][u], cnt[u], lane);
    __syncwarp();

    // fused Stage 8+9 MLP (ascending (d2, orig idx) == reference order)
    #pragma unroll
    for (int u = 0; u < QPW; ++u) {
        unsigned long long* w = wb[wid][u];
        float acc = 0.f;
        for (int j = 0; j < KT; ++j) {
            unsigned long long kk = w[j];
            int nj = (int)(unsigned)kk;
            float d2 = __uint_as_float((unsigned)(kk >> 32));
            float r3 = sqrtf(d2 + 1e-12f);
            float4 b4 = g_bary4[nj];
            float d0 = b4.x - qx[u], d1 = b4.y - qy[u], d2w = b4.z - qz[u];
            float pj = b4.w;
            float part = 0.f;
            #pragma unroll
            for (int v = 0; v < 4; ++v) {
                int k = v * 32 + lane; // conflict-free shared access
                float h = d0 * w1s[k] + d1 * w1s[HID + k] + d2w * w1s[2 * HID + k]
                        + r3 * w1s[3 * HID + k] + b1s[k];
                h = h > 0.f ? h : 0.f;
                part += h * w2s[k];
            }
            acc += part * pj;
        }
        #pragma unroll
        for (int o = 16; o > 0; o >>= 1) acc += __shfl_down_sync(0xffffffffu, acc, o);
        if (lane == 0) {
            float fs = pw[u] * acc;
            g_sort[qo[u]] = ((unsigned long long)fdesc(fs) << 32) | (unsigned)qo[u];
        }
    }
}

// ---------------- Stage 10a: per-2048-chunk sort, keep smallest 1024 ----------------
__global__ void __launch_bounds__(1024)
k_sortchunks() {
    __shared__ unsigned long long s[2048];
    int tid = threadIdx.x;
    int base = blockIdx.x * 2048;   // 32 chunks
    s[tid] = g_sort[base + tid];
    s[tid + 1024] = g_sort[base + tid + 1024];
    __syncthreads();
    for (int size = 2; size <= 2048; size <<= 1) {
        for (int stride = size >> 1; stride > 0; stride >>= 1) {
            int i = ((tid & ~(stride - 1)) << 1) | (tid & (stride - 1));
            int j = i | stride;
            bool up = ((i & size) == 0);
            unsigned long long a = s[i], b = s[j];
            if ((a > b) == up) { s[i] = b; s[j] = a; }
            __syncthreads();
        }
    }
    g_topA[blockIdx.x * 1024 + tid] = s[tid]; // smallest 1024, ascending
}

// ---------------- Stage 10b: merge-prune two sorted-1024 lists -> smallest 1024 ----------------
__global__ void __launch_bounds__(1024)
k_merge(int srcA) {
    const unsigned long long* in = srcA ? g_topA : g_topB;
    unsigned long long*       out = srcA ? g_topB : g_topA;
    __shared__ unsigned long long s[2048];
    int tid = threadIdx.x;
    int p = blockIdx.x;
    s[tid] = in[(2 * p) * 1024 + tid];
    s[1024 + tid] = in[(2 * p + 1) * 1024 + (1023 - tid)]; // reversed -> bitonic
    __syncthreads();
    {   // keep min-half
        unsigned long long a = s[tid], b = s[tid + 1024];
        s[tid] = a < b ? a : b;
    }
    __syncthreads();
    for (int stride = 512; stride > 0; stride >>= 1) {
        if (tid < 512) {
            int i = ((tid & ~(stride - 1)) << 1) | (tid & (stride - 1));
            int j = i | stride;
            unsigned long long a = s[i], b = s[j];
            if (a > b) { s[i] = b; s[j] = a; }
        }
        __syncthreads();
    }
    out[p * 1024 + tid] = s[tid];
}

// ---------------- Stage 10c: output gather ----------------
__global__ void k_out(float* __restrict__ out) {
    int t = blockIdx.x * blockDim.x + threadIdx.x;
    if (t >= TT) return;
    unsigned tri = (unsigned)g_topB[t];
    int i = (int)tri / 14, j = (int)tri % 14;
    int v1 = g_knn[i * KNNK + j], v2 = g_knn[i * KNNK + j + 1];
    #pragma unroll
    for (int d = 0; d < 3; ++d) {
        out[t * 9 + d]     = g_ext[3 * i + d];
        out[t * 9 + 3 + d] = g_ext[3 * v1 + d];
        out[t * 9 + 6 + d] = g_ext[3 * v2 + d];
    }
}

// ---------------- host driver ----------------
extern "C" void kernel_launch(void* const* d_in, const int* in_sizes, int n_in,
                              void* d_out, int out_size) {
    const float* nodes = (const float*)d_in[0];
    const int*   adj   = (const int*)d_in[1];
    int base = (n_in >= 10 && in_sizes[2] == 1) ? 3 : 2;
    const float* Wg   = (const float*)d_in[base + 0];
    const float* wg   = (const float*)d_in[base + 1];
    const float* Wd   = (const float*)d_in[base + 2];
    const float* aatt = (const float*)d_in[base + 3];
    const float* W1   = (const float*)d_in[base + 4];
    const float* b1   = (const float*)d_in[base + 5];
    const float* W2   = (const float*)d_in[base + 6];
    float* out = (float*)d_out;

    // Stage 1 + stage-2 sort (N=8192 full bitonic, order must match lax.top_k)
    k_gnn<<<NN, 64>>>(nodes, adj, Wg, wg);
    k_bitonic_local<<<NN / 2048, 1024>>>();
    for (int size = 4096; size <= NN; size <<= 1) {
        for (int stride = size >> 1; stride >= 2048; stride >>= 1)
            k_bitonic_global<<<(NN / 2 + 255) / 256, 256>>>(size, stride, NN / 2);
        k_bitonic_tail<<<NN / 2048, 1024>>>(size);
    }
    k_gather_ext<<<(MM + 255) / 256, 256>>>(nodes);

    k_knn16<<<MM / 8, 256>>>();
    k_dev<<<MM, 64>>>(Wd);
    k_soft<<<(MM + 255) / 256, 256>>>(aatt);

    // spatial reorder of triangle barycenters
    k_init<<<NCELL / 256, 256>>>();
    k_tri<<<SORTN / 256, 256>>>();
    k_cellcount<<<NTRI / 256, 256>>>();
    k_prefix<<<1, 1024>>>();
    k_scatter<<<NTRI / 256, 256>>>();
    k_tilebbox<<<NTILE, 256>>>();

    k_knn20<<<NTRI / (8 * QPW), 256>>>(W1, b1, W2);

    // Stage 10: exact top-1024 via chunk-sort + 5 merge-prune rounds
    k_sortchunks<<<32, 1024>>>();
    k_merge<<<16, 1024>>>(1); // A -> B
    k_merge<<<8, 1024>>>(0);  // B -> A
    k_merge<<<4, 1024>>>(1);  // A -> B
    k_merge<<<2, 1024>>>(0);  // B -> A
    k_merge<<<1, 1024>>>(1);  // A -> B (final sorted 1024 in g_topB)

    k_out<<<(TT + 255) / 256, 256>>>(out);
}

// round 11
// speedup vs baseline: 4.3804x; 1.3881x over previous
#include <cuda_runtime.h>

#define NN    8192
#define K0    16
#define MM    3072
#define KNNK  15
#define TT    1024
#define NTRI  43008      // MM * 14 = 21 * 2048
#define KT    20
#define HID   128
#define SORTN 65536
#define QPW   4          // queries per warp in knn20
#define NCELL 4096       // 16^3 morton cells
#define NTILE 21         // NTRI / 2048
#define NSUB  (NTILE * 4)

// ---------------- scratch (static device globals; no allocation) ----------------
__device__ unsigned long long g_keysN[NN];       // stage-2 sort keys
__device__ float              g_ext[MM * 3];     // selected points (AoS xyz)
__device__ float4             g_ext4[MM];        // packed for knn16 tiles
__device__ int                g_knn[MM * KNNK];
__device__ float              g_f[MM];
__device__ float              g_S[MM * KNNK];
__device__ float4             g_bary4[NTRI];     // xyz + p_init in w (ORIGINAL order)
__device__ float4             g_bary4p[NTRI];    // spatially permuted
__device__ int                g_oidx[NTRI];      // permuted pos -> original idx
__device__ unsigned           g_bb[6];           // enc-mapped global bbox lo xyz, hi xyz
__device__ int                g_cellcnt[NCELL];
__device__ int                g_celloff[NCELL];
__device__ float              g_subbb[NSUB][6];  // per-512 sub-tile bboxes
__device__ unsigned long long g_sort[SORTN];     // stage-10 score keys (padded)
__device__ unsigned long long g_topA[32 * 1024]; // merge-prune ping
__device__ unsigned long long g_topB[16 * 1024]; // merge-prune pong

// order-preserving float->u32 map, inverted for DESCENDING sort via ascending keys
__device__ __forceinline__ unsigned fdesc(float v) {
    unsigned fb  = __float_as_uint(v);
    unsigned asc = (fb & 0x80000000u) ? ~fb : (fb | 0x80000000u);
    return ~asc;
}
// monotone-ascending float<->u32 maps (for atomic min/max bbox)
__device__ __forceinline__ unsigned fenc(float v) {
    unsigned u = __float_as_uint(v);
    return (u & 0x80000000u) ? ~u : (u | 0x80000000u);
}
__device__ __forceinline__ float fdec(unsigned u) {
    return (u & 0x80000000u) ? __uint_as_float(u ^ 0x80000000u) : __uint_as_float(~u);
}

// ---------------- generic bitonic flush: sort 64-entry warp area ascending, keep [0..K-1] ----------------
template <int K>
__device__ __forceinline__ void flushK(unsigned long long* w, int cnt, int lane) {
    for (int t = K + cnt + lane; t < 64; t += 32) w[t] = ~0ULL;
    __syncwarp();
    #pragma unroll
    for (int size = 2; size <= 64; size <<= 1) {
        #pragma unroll
        for (int stride = size >> 1; stride > 0; stride >>= 1) {
            int i = ((lane & ~(stride - 1)) << 1) | (lane & (stride - 1));
            int j = i | stride;
            bool up = ((i & size) == 0);
            unsigned long long a = w[i], b = w[j];
            if ((a > b) == up) { w[i] = b; w[j] = a; }
            __syncwarp();
        }
    }
}

// ---------------- Stage 1: GNN inclusion scores ----------------
__global__ void k_gnn(const float* __restrict__ nodes, const int* __restrict__ adj,
                      const float* __restrict__ Wg, const float* __restrict__ wg) {
    int i = blockIdx.x;
    int c = threadIdx.x; // 0..63
    float qx = nodes[3 * i], qy = nodes[3 * i + 1], qz = nodes[3 * i + 2];
    float w0 = Wg[c], w1 = Wg[64 + c], w2 = Wg[128 + c];
    float h = 0.f;
    #pragma unroll 4
    for (int k = 0; k < K0; ++k) {
        int nb = adj[i * K0 + k];
        float dx = qx - nodes[3 * nb], dy = qy - nodes[3 * nb + 1], dz = qz - nodes[3 * nb + 2];
        float v = dx * w0 + dy * w1 + dz * w2;
        v = v > 0.f ? v : 0.f;
        h = fmaxf(h, v);
    }
    __shared__ float red[64];
    red[c] = h * wg[c];
    __syncthreads();
    for (int s = 32; s > 0; s >>= 1) {
        if (c < s) red[c] += red[c + s];
        __syncthreads();
    }
    if (c == 0) {
        g_keysN[i] = ((unsigned long long)fdesc(red[0]) << 32) | (unsigned)i;
    }
}

// ---------------- bitonic sort for stage-2 keys (N=8192 only) ----------------
__global__ void k_bitonic_local() {
    __shared__ unsigned long long s[2048];
    int tid = threadIdx.x;
    int base = blockIdx.x * 2048;
    s[tid] = g_keysN[base + tid];
    s[tid + 1024] = g_keysN[base + tid + 1024];
    __syncthreads();
    for (int size = 2; size <= 2048; size <<= 1) {
        for (int stride = size >> 1; stride > 0; stride >>= 1) {
            int i = ((tid & ~(stride - 1)) << 1) | (tid & (stride - 1));
            int j = i | stride;
            bool up = (((base + i) & size) == 0);
            unsigned long long a = s[i], b = s[j];
            if ((a > b) == up) { s[i] = b; s[j] = a; }
            __syncthreads();
        }
    }
    g_keysN[base + tid] = s[tid];
    g_keysN[base + tid + 1024] = s[tid + 1024];
}

__global__ void k_bitonic_global(int size, int stride, int nhalf) {
    int t = blockIdx.x * blockDim.x + threadIdx.x;
    if (t >= nhalf) return;
    int i = ((t & ~(stride - 1)) << 1) | (t & (stride - 1));
    int j = i | stride;
    bool up = ((i & size) == 0);
    unsigned long long a = g_keysN[i], b = g_keysN[j];
    if ((a > b) == up) { g_keysN[i] = b; g_keysN[j] = a; }
}

__global__ void k_bitonic_tail(int size) {
    __shared__ unsigned long long s[2048];
    int tid = threadIdx.x;
    int base = blockIdx.x * 2048;
    s[tid] = g_keysN[base + tid];
    s[tid + 1024] = g_keysN[base + tid + 1024];
    __syncthreads();
    bool up = ((base & size) == 0);
    for (int stride = 1024; stride > 0; stride >>= 1) {
        int i = ((tid & ~(stride - 1)) << 1) | (tid & (stride - 1));
        int j = i | stride;
        unsigned long long a = s[i], b = s[j];
        if ((a > b) == up) { s[i] = b; s[j] = a; }
        __syncthreads();
    }
    g_keysN[base + tid] = s[tid];
    g_keysN[base + tid + 1024] = s[tid + 1024];
}

// ---------------- Stage 2: gather selected points ----------------
__global__ void k_gather_ext(const float* __restrict__ nodes) {
    int m = blockIdx.x * blockDim.x + threadIdx.x;
    if (m >= MM) return;
    int idx = (int)(unsigned)g_keysN[m];
    float x = nodes[3 * idx], y = nodes[3 * idx + 1], z = nodes[3 * idx + 2];
    g_ext[3 * m] = x; g_ext[3 * m + 1] = y; g_ext[3 * m + 2] = z;
    g_ext4[m] = make_float4(x, y, z, 0.f);
}

// ---------------- Stage 3: exact 16-NN, batched append + bitonic flush ----------------
__global__ void __launch_bounds__(256)
k_knn16() {
    __shared__ float4 st[2048];
    __shared__ unsigned long long wb[8][64];
    int tid = threadIdx.x, lane = tid & 31, wid = tid >> 5;
    int q = blockIdx.x * 8 + wid;     // grid = MM/8
    unsigned long long* w = wb[wid];
    if (lane < 16) w[lane] = 0x7F800000FFFFFFFFull; // d2=+inf, idx=max

    float qx = g_ext[3 * q], qy = g_ext[3 * q + 1], qz = g_ext[3 * q + 2];
    float thrd = __uint_as_float(0x7F800000u); // +inf
    int cnt = 0;

    for (int tile = 0; tile < 2; ++tile) {
        int base = tile * 2048;
        int n = (tile == 0) ? 2048 : (MM - 2048);
        __syncthreads();
        for (int t = tid; t < n; t += 256) st[t] = g_ext4[base + t];
        __syncthreads();
        int iters = n >> 5;
        #pragma unroll 4
        for (int s = 0; s < iters; ++s) {
            int c = (s << 5) | lane;
            float4 cc = st[c];
            float dx = qx - cc.x, dy = qy - cc.y, dz = qz - cc.z;
            float d2 = dx * dx + dy * dy + dz * dz;
            bool pass = d2 <= thrd;
            unsigned mask = __ballot_sync(0xffffffffu, pass);
            if (mask) {
                int pop = __popc(mask);
                if (cnt + pop > 48) {
                    flushK<16>(w, cnt, lane);
                    cnt = 0;
                    thrd = __uint_as_float((unsigned)(w[15] >> 32)); // exact 16th d2
                }
                if (pass) {
                    unsigned long long key =
                        ((unsigned long long)__float_as_uint(d2) << 32) | (unsigned)(base + c);
                    w[16 + cnt + __popc(mask & ((1u << lane) - 1u))] = key;
                }
                cnt += pop;
                __syncwarp();
            }
        }
    }
    if (cnt) flushK<16>(w, cnt, lane);
    __syncwarp();
    if (lane >= 1 && lane < 16)
        g_knn[q * KNNK + lane - 1] = (int)(unsigned)w[lane]; // drop self (w[0])
}

// ---------------- Stage 4: DevConv edge feature mean ----------------
__global__ void k_dev(const float* __restrict__ Wd) {
    int i = blockIdx.x, c = threadIdx.x; // 64 threads
    __shared__ float nb[KNNK][3];
    __shared__ float red[64];
    if (c < KNNK * 3) {
        int k = c / 3, d = c % 3;
        nb[k][d] = g_ext[3 * g_knn[i * KNNK + k] + d];
    }
    __syncthreads();
    float qx = g_ext[3 * i], qy = g_ext[3 * i + 1], qz = g_ext[3 * i + 2];
    float w0 = Wd[c], w1 = Wd[64 + c], w2 = Wd[128 + c];
    float m = 0.f;
    #pragma unroll
    for (int k = 0; k < KNNK; ++k) {
        float v = (nb[k][0] - qx) * w0 + (nb[k][1] - qy) * w1 + (nb[k][2] - qz) * w2;
        v = v > 0.f ? v : 0.f;
        m = fmaxf(m, v);
    }
    red[c] = m;
    __syncthreads();
    for (int s = 32; s > 0; s >>= 1) {
        if (c < s) red[c] += red[c + s];
        __syncthreads();
    }
    if (c == 0) g_f[i] = red[0] * (1.f / 64.f);
}

// ---------------- Stage 5: softmax over knn edges ----------------
__global__ void k_soft(const float* __restrict__ a_att) {
    int i = blockIdx.x * blockDim.x + threadIdx.x;
    if (i >= MM) return;
    float a0 = a_att[0], a1 = a_att[1];
    float fi = g_f[i];
    float l[KNNK];
    float mx = -1e30f;
    #pragma unroll
    for (int j = 0; j < KNNK; ++j) {
        l[j] = a0 * fi + a1 * g_f[g_knn[i * KNNK + j]];
        mx = fmaxf(mx, l[j]);
    }
    float s = 0.f;
    #pragma unroll
    for (int j = 0; j < KNNK; ++j) { l[j] = expf(l[j] - mx); s += l[j]; }
    float inv = 1.f / s;
    #pragma unroll
    for (int j = 0; j < KNNK; ++j) g_S[i * KNNK + j] = l[j] * inv;
}

// ---------------- init: zero cell counters + bbox accumulators ----------------
__global__ void k_init() {
    int t = blockIdx.x * blockDim.x + threadIdx.x;
    if (t < NCELL) g_cellcnt[t] = 0;
    if (t < 3) g_bb[t] = 0xFFFFFFFFu;
    else if (t < 6) g_bb[t] = 0u;
}

// ---------------- Stage 6/7a: p_init + barycenters + pad + bbox reduce ----------------
__global__ void k_tri() {
    __shared__ unsigned sbb[6];
    if (threadIdx.x < 3) sbb[threadIdx.x] = 0xFFFFFFFFu;
    else if (threadIdx.x < 6) sbb[threadIdx.x] = 0u;
    __syncthreads();
    int t = blockIdx.x * blockDim.x + threadIdx.x; // grid covers SORTN
    if (t < SORTN && t >= NTRI) g_sort[t] = ~0ULL;
    if (t < NTRI) {
        int i = t / 14, j = t % 14;
        int a = g_knn[i * KNNK + j], b = g_knn[i * KNNK + j + 1];
        float p = g_S[i * KNNK + j] * g_S[i * KNNK + j + 1];
        float bx = (g_ext[3 * i] + g_ext[3 * a] + g_ext[3 * b]) * (1.f / 3.f);
        float by = (g_ext[3 * i + 1] + g_ext[3 * a + 1] + g_ext[3 * b + 1]) * (1.f / 3.f);
        float bz = (g_ext[3 * i + 2] + g_ext[3 * a + 2] + g_ext[3 * b + 2]) * (1.f / 3.f);
        g_bary4[t] = make_float4(bx, by, bz, p);
        atomicMin(&sbb[0], fenc(bx)); atomicMin(&sbb[1], fenc(by)); atomicMin(&sbb[2], fenc(bz));
        atomicMax(&sbb[3], fenc(bx)); atomicMax(&sbb[4], fenc(by)); atomicMax(&sbb[5], fenc(bz));
    }
    __syncthreads();
    if (threadIdx.x < 3) atomicMin(&g_bb[threadIdx.x], sbb[threadIdx.x]);
    else if (threadIdx.x < 6) atomicMax(&g_bb[threadIdx.x], sbb[threadIdx.x]);
}

// ---------------- morton cell id (16^3) ----------------
__device__ __forceinline__ int cellof(float x, float y, float z) {
    float lox = fdec(g_bb[0]), loy = fdec(g_bb[1]), loz = fdec(g_bb[2]);
    float hix = fdec(g_bb[3]), hiy = fdec(g_bb[4]), hiz = fdec(g_bb[5]);
    int cx = (int)((x - lox) / (hix - lox) * 16.f);
    int cy = (int)((y - loy) / (hiy - loy) * 16.f);
    int cz = (int)((z - loz) / (hiz - loz) * 16.f);
    cx = min(max(cx, 0), 15); cy = min(max(cy, 0), 15); cz = min(max(cz, 0), 15);
    int cell = 0;
    #pragma unroll
    for (int i = 0; i < 4; ++i) {
        cell |= (((cx >> i) & 1) << (3 * i + 2)) | (((cy >> i) & 1) << (3 * i + 1))
              | (((cz >> i) & 1) << (3 * i));
    }
    return cell;
}

__global__ void k_cellcount() {
    int t = blockIdx.x * blockDim.x + threadIdx.x;
    if (t >= NTRI) return;
    float4 b4 = g_bary4[t];
    atomicAdd(&g_cellcnt[cellof(b4.x, b4.y, b4.z)], 1);
}

// exclusive prefix over 4096 cells; single block of 1024 threads, 4 cells each
__global__ void __launch_bounds__(1024)
k_prefix() {
    __shared__ int s[1024];
    int tid = threadIdx.x;
    int c0 = g_cellcnt[4 * tid], c1 = g_cellcnt[4 * tid + 1];
    int c2 = g_cellcnt[4 * tid + 2], c3 = g_cellcnt[4 * tid + 3];
    int sum = c0 + c1 + c2 + c3;
    s[tid] = sum;
    __syncthreads();
    for (int off = 1; off < 1024; off <<= 1) {
        int v = s[tid];
        if (tid >= off) v += s[tid - off];
        __syncthreads();
        s[tid] = v;
        __syncthreads();
    }
    int base = s[tid] - sum; // exclusive
    g_celloff[4 * tid] = base;
    g_celloff[4 * tid + 1] = base + c0;
    g_celloff[4 * tid + 2] = base + c0 + c1;
    g_celloff[4 * tid + 3] = base + c0 + c1 + c2;
}

__global__ void k_scatter() {
    int t = blockIdx.x * blockDim.x + threadIdx.x;
    if (t >= NTRI) return;
    float4 b4 = g_bary4[t];
    int pos = atomicAdd(&g_celloff[cellof(b4.x, b4.y, b4.z)], 1);
    g_bary4p[pos] = b4;
    g_oidx[pos] = t;
}

// per-512 sub-tile bbox over the permuted array (one block per sub-tile)
__global__ void __launch_bounds__(256)
k_subbbox() {
    __shared__ unsigned sbb[6];
    if (threadIdx.x < 3) sbb[threadIdx.x] = 0xFFFFFFFFu;
    else if (threadIdx.x < 6) sbb[threadIdx.x] = 0u;
    __syncthreads();
    int base = blockIdx.x * 512;
    for (int i = threadIdx.x; i < 512; i += 256) {
        float4 b4 = g_bary4p[base + i];
        atomicMin(&sbb[0], fenc(b4.x)); atomicMin(&sbb[1], fenc(b4.y)); atomicMin(&sbb[2], fenc(b4.z));
        atomicMax(&sbb[3], fenc(b4.x)); atomicMax(&sbb[4], fenc(b4.y)); atomicMax(&sbb[5], fenc(b4.z));
    }
    __syncthreads();
    if (threadIdx.x < 6) g_subbb[blockIdx.x][threadIdx.x] = fdec(sbb[threadIdx.x]);
}

// ---------------- Stage 7/8/9 fused: sub-tile-pruned streaming 20-NN + MLP ----------------
__global__ void __launch_bounds__(256)
k_knn20(const float* __restrict__ W1, const float* __restrict__ b1,
        const float* __restrict__ W2) {
    __shared__ float sx[2048], sy[2048], sz[2048];
    __shared__ int so[2048];
    __shared__ float w1s[4 * HID], b1s[HID], w2s[HID];
    __shared__ unsigned long long wb[8][QPW][64];
    __shared__ int needs[8];
    int tid = threadIdx.x, lane = tid & 31, wid = tid >> 5;
    int pbase = (blockIdx.x * 8 + wid) * QPW;   // PERMUTED query positions
    int home = (blockIdx.x * 32) >> 11;         // tile containing this block's queries
    int homesub = (pbase >> 9) & 3;             // warp's home sub within its tile

    for (int t = tid; t < 4 * HID; t += 256) w1s[t] = W1[t];
    if (tid < HID) { b1s[tid] = b1[tid]; w2s[tid] = W2[tid]; }
    if (lane < KT) {
        #pragma unroll
        for (int u = 0; u < QPW; ++u) wb[wid][u][lane] = 0x7F800000FFFFFFFFull;
    }

    float qx[QPW], qy[QPW], qz[QPW], pw[QPW], thr[QPW];
    int qo[QPW], cnt[QPW];
    #pragma unroll
    for (int u = 0; u < QPW; ++u) {
        float4 qb = g_bary4p[pbase + u];
        qx[u] = qb.x; qy[u] = qb.y; qz[u] = qb.z; pw[u] = qb.w;
        qo[u] = g_oidx[pbase + u];
        thr[u] = __uint_as_float(0x7F800000u); // +inf
        cnt[u] = 0;
    }

    for (int tt = 0; tt < NTILE; ++tt) {
        int tile = home + tt; if (tile >= NTILE) tile -= NTILE;
        // per-warp sub-tile need mask (exact bbox prune per 512-candidate sub)
        unsigned smask = 0;
        #pragma unroll
        for (int ss = 0; ss < 4; ++ss) {
            int sub = (homesub + ss) & 3;
            const float* bb = g_subbb[tile * 4 + sub];
            float lx = bb[0], ly = bb[1], lz = bb[2];
            float hx = bb[3], hy = bb[4], hz = bb[5];
            bool need = false;
            #pragma unroll
            for (int u = 0; u < QPW; ++u) {
                float ddx = fmaxf(fmaxf(lx - qx[u], qx[u] - hx), 0.f);
                float ddy = fmaxf(fmaxf(ly - qy[u], qy[u] - hy), 0.f);
                float ddz = fmaxf(fmaxf(lz - qz[u], qz[u] - hz), 0.f);
                need |= (ddx * ddx + ddy * ddy + ddz * ddz) <= thr[u];
            }
            if (need) smask |= 1u << sub;
        }
        if (lane == 0) needs[wid] = (int)smask;
        __syncthreads();   // needs visible; all warps done with previous tile buffer
        unsigned bmask = 0;
        #pragma unroll
        for (int wv = 0; wv < 8; ++wv) bmask |= (unsigned)needs[wv];
        if (!bmask) continue;    // uniform across block

        int base = tile * 2048;
        #pragma unroll
        for (int sub = 0; sub < 4; ++sub) {
            if (!((bmask >> sub) & 1)) continue;
            for (int t = tid; t < 512; t += 256) {
                int c = (sub << 9) + t;
                float4 b4 = g_bary4p[base + c];
                sx[c] = b4.x; sy[c] = b4.y; sz[c] = b4.z;
                so[c] = g_oidx[base + c];
            }
        }
        __syncthreads();

        #pragma unroll
        for (int ss = 0; ss < 4; ++ss) {
            int sub = (homesub + ss) & 3;
            if (!((smask >> sub) & 1)) continue;
            for (int s = 0; s < 16; ++s) {
                int c = (sub << 9) + (s << 5) + lane;
                float cx = sx[c], cy = sy[c], cz = sz[c];
                float d2v[QPW];
                bool pass[QPW];
                bool any = false;
                #pragma unroll
                for (int u = 0; u < QPW; ++u) {
                    float dx = qx[u] - cx, dy = qy[u] - cy, dz = qz[u] - cz;
                    d2v[u] = dx * dx + dy * dy + dz * dz;
                    pass[u] = d2v[u] <= thr[u];
                    any |= pass[u];
                }
                if (__any_sync(0xffffffffu, any)) {
                    int oi = so[c];      // ORIGINAL candidate index (exact tie-break)
                    #pragma unroll
                    for (int u = 0; u < QPW; ++u) {
                        unsigned mu = __ballot_sync(0xffffffffu, pass[u]);
                        if (mu) {
                            int pop = __popc(mu);
                            unsigned long long* w = wb[wid][u];
                            if (cnt[u] + pop > 44) {          // batch-prune first
                                flushK<20>(w, cnt[u], lane);
                                cnt[u] = 0;
                                thr[u] = __uint_as_float((unsigned)(w[19] >> 32)); // exact 20th d2
                            }
                            if (pass[u]) {                    // parallel append
                                unsigned long long key =
                                    ((unsigned long long)__float_as_uint(d2v[u]) << 32) | (unsigned)oi;
                                w[20 + cnt[u] + __popc(mu & ((1u << lane) - 1u))] = key;
                            }
                            cnt[u] += pop;
                        }
                    }
                    __syncwarp();
                }
            }
        }
    }
    #pragma unroll
    for (int u = 0; u < QPW; ++u)
        if (cnt[u]) flushK<20>(wb[wid][u], cnt[u], lane);
    __syncwarp();

    // fused Stage 8+9 MLP (ascending (d2, orig idx) == reference order)
    #pragma unroll
    for (int u = 0; u < QPW; ++u) {
        unsigned long long* w = wb[wid][u];
        float acc = 0.f;
        for (int j = 0; j < KT; ++j) {
            unsigned long long kk = w[j];
            int nj = (int)(unsigned)kk;
            float d2 = __uint_as_float((unsigned)(kk >> 32));
            float r3 = sqrtf(d2 + 1e-12f);
            float4 b4 = g_bary4[nj];
            float d0 = b4.x - qx[u], d1 = b4.y - qy[u], d2w = b4.z - qz[u];
            float pj = b4.w;
            float part = 0.f;
            #pragma unroll
            for (int v = 0; v < 4; ++v) {
                int k = v * 32 + lane; // conflict-free shared access
                float h = d0 * w1s[k] + d1 * w1s[HID + k] + d2w * w1s[2 * HID + k]
                        + r3 * w1s[3 * HID + k] + b1s[k];
                h = h > 0.f ? h : 0.f;
                part += h * w2s[k];
            }
            acc += part * pj;
        }
        #pragma unroll
        for (int o = 16; o > 0; o >>= 1) acc += __shfl_down_sync(0xffffffffu, acc, o);
        if (lane == 0) {
            float fs = pw[u] * acc;
            g_sort[qo[u]] = ((unsigned long long)fdesc(fs) << 32) | (unsigned)qo[u];
        }
    }
}

// ---------------- Stage 10a: per-2048-chunk sort, keep smallest 1024 ----------------
__global__ void __launch_bounds__(1024)
k_sortchunks() {
    __shared__ unsigned long long s[2048];
    int tid = threadIdx.x;
    int base = blockIdx.x * 2048;   // 32 chunks
    s[tid] = g_sort[base + tid];
    s[tid + 1024] = g_sort[base + tid + 1024];
    __syncthreads();
    for (int size = 2; size <= 2048; size <<= 1) {
        for (int stride = size >> 1; stride > 0; stride >>= 1) {
            int i = ((tid & ~(stride - 1)) << 1) | (tid & (stride - 1));
            int j = i | stride;
            bool up = ((i & size) == 0);
            unsigned long long a = s[i], b = s[j];
            if ((a > b) == up) { s[i] = b; s[j] = a; }
            __syncthreads();
        }
    }
    g_topA[blockIdx.x * 1024 + tid] = s[tid]; // smallest 1024, ascending
}

// ---------------- Stage 10b: merge-prune two sorted-1024 lists -> smallest 1024 ----------------
__global__ void __launch_bounds__(1024)
k_merge(int srcA) {
    const unsigned long long* in = srcA ? g_topA : g_topB;
    unsigned long long*       out = srcA ? g_topB : g_topA;
    __shared__ unsigned long long s[2048];
    int tid = threadIdx.x;
    int p = blockIdx.x;
    s[tid] = in[(2 * p) * 1024 + tid];
    s[1024 + tid] = in[(2 * p + 1) * 1024 + (1023 - tid)]; // reversed -> bitonic
    __syncthreads();
    {   // keep min-half
        unsigned long long a = s[tid], b = s[tid + 1024];
        s[tid] = a < b ? a : b;
    }
    __syncthreads();
    for (int stride = 512; stride > 0; stride >>= 1) {
        if (tid < 512) {
            int i = ((tid & ~(stride - 1)) << 1) | (tid & (stride - 1));
            int j = i | stride;
            unsigned long long a = s[i], b = s[j];
            if (a > b) { s[i] = b; s[j] = a; }
        }
        __syncthreads();
    }
    out[p * 1024 + tid] = s[tid];
}

// ---------------- Stage 10c: output gather ----------------
__global__ void k_out(float* __restrict__ out) {
    int t = blockIdx.x * blockDim.x + threadIdx.x;
    if (t >= TT) return;
    unsigned tri = (unsigned)g_topB[t];
    int i = (int)tri / 14, j = (int)tri % 14;
    int v1 = g_knn[i * KNNK + j], v2 = g_knn[i * KNNK + j + 1];
    #pragma unroll
    for (int d = 0; d < 3; ++d) {
        out[t * 9 + d]     = g_ext[3 * i + d];
        out[t * 9 + 3 + d] = g_ext[3 * v1 + d];
        out[t * 9 + 6 + d] = g_ext[3 * v2 + d];
    }
}

// ---------------- host driver ----------------
extern "C" void kernel_launch(void* const* d_in, const int* in_sizes, int n_in,
                              void* d_out, int out_size) {
    const float* nodes = (const float*)d_in[0];
    const int*   adj   = (const int*)d_in[1];
    int base = (n_in >= 10 && in_sizes[2] == 1) ? 3 : 2;
    const float* Wg   = (const float*)d_in[base + 0];
    const float* wg   = (const float*)d_in[base + 1];
    const float* Wd   = (const float*)d_in[base + 2];
    const float* aatt = (const float*)d_in[base + 3];
    const float* W1   = (const float*)d_in[base + 4];
    const float* b1   = (const float*)d_in[base + 5];
    const float* W2   = (const float*)d_in[base + 6];
    float* out = (float*)d_out;

    // Stage 1 + stage-2 sort (N=8192 full bitonic, order must match lax.top_k)
    k_gnn<<<NN, 64>>>(nodes, adj, Wg, wg);
    k_bitonic_local<<<NN / 2048, 1024>>>();
    for (int size = 4096; size <= NN; size <<= 1) {
        for (int stride = size >> 1; stride >= 2048; stride >>= 1)
            k_bitonic_global<<<(NN / 2 + 255) / 256, 256>>>(size, stride, NN / 2);
        k_bitonic_tail<<<NN / 2048, 1024>>>(size);
    }
    k_gather_ext<<<(MM + 255) / 256, 256>>>(nodes);

    k_knn16<<<MM / 8, 256>>>();
    k_dev<<<MM, 64>>>(Wd);
    k_soft<<<(MM + 255) / 256, 256>>>(aatt);

    // spatial reorder of triangle barycenters
    k_init<<<NCELL / 256, 256>>>();
    k_tri<<<SORTN / 256, 256>>>();
    k_cellcount<<<NTRI / 256, 256>>>();
    k_prefix<<<1, 1024>>>();
    k_scatter<<<NTRI / 256, 256>>>();
    k_subbbox<<<NSUB, 256>>>();

    k_knn20<<<NTRI / (8 * QPW), 256>>>(W1, b1, W2);

    // Stage 10: exact top-1024 via chunk-sort + 5 merge-prune rounds
    k_sortchunks<<<32, 1024>>>();
    k_merge<<<16, 1024>>>(1); // A -> B
    k_merge<<<8, 1024>>>(0);  // B -> A
    k_merge<<<4, 1024>>>(1);  // A -> B
    k_merge<<<2, 1024>>>(0);  // B -> A
    k_merge<<<1, 1024>>>(1);  // A -> B (final sorted 1024 in g_topB)

    k_out<<<(TT + 255) / 256, 256>>>(out);
}